// round 1
// baseline (speedup 1.0000x reference)
#include <cuda_runtime.h>
#include <math.h>

// Problem constants
#define NPTS 16384
#define KNB  32
#define PKP  15
#define CIN  256
#define CMID 128
#define COUT 512
#define PC   (PKP * CMID)   // 1920

// Scratch (device globals -- allocation-free)
__device__ float g_h  [(size_t)NPTS * CMID];        // 8 MB
__device__ float g_agg[(size_t)NPTS * PC];          // 126 MB
__device__ float g_mid[(size_t)NPTS * CMID];        // 8 MB
__device__ float g_y  [(size_t)NPTS * COUT];        // 32 MB
__device__ float g_stats[2 * COUT];

// ---------------------------------------------------------------------------
// Classic register-blocked SGEMM: C[M,N] = A[M,K] @ B[K,N] (+ bias)
// BM=BN=128, BK=16, TM=TN=8, 256 threads. All dims divide evenly here.
// ---------------------------------------------------------------------------
__global__ void __launch_bounds__(256)
sgemm_bias(const float* __restrict__ A, const float* __restrict__ B,
           const float* __restrict__ bias, float* __restrict__ C,
           int M, int N, int K)
{
    constexpr int BM = 128, BN = 128, BK = 16, TM = 8, TN = 8;
    __shared__ float As[BK][BM];
    __shared__ float Bs[BK][BN];

    const int tid  = threadIdx.x;
    const int cCol = blockIdx.x;   // N tile
    const int cRow = blockIdx.y;   // M tile

    const int tx = tid % (BN / TN);   // 0..15
    const int ty = tid / (BN / TN);   // 0..15

    float acc[TM][TN];
#pragma unroll
    for (int i = 0; i < TM; i++)
#pragma unroll
        for (int j = 0; j < TN; j++) acc[i][j] = 0.0f;

    // A tile: 128x16 floats = 512 float4, 256 thr -> 2 each
    const int aRow = tid / (BK / 4);        // 0..63
    const int aCol = (tid % (BK / 4)) * 4;  // 0,4,8,12
    // B tile: 16x128 floats = 512 float4, 256 thr -> 2 each
    const int bRow = tid / (BN / 4);        // 0..7
    const int bCol = (tid % (BN / 4)) * 4;  // 0..124

    const float* Aptr = A + (size_t)cRow * BM * K;
    const float* Bptr = B + (size_t)cCol * BN;

    for (int kt = 0; kt < K; kt += BK) {
#pragma unroll
        for (int i = 0; i < 2; i++) {
            int r = aRow + i * 64;
            float4 v = *reinterpret_cast<const float4*>(Aptr + (size_t)r * K + kt + aCol);
            As[aCol + 0][r] = v.x;
            As[aCol + 1][r] = v.y;
            As[aCol + 2][r] = v.z;
            As[aCol + 3][r] = v.w;
        }
#pragma unroll
        for (int i = 0; i < 2; i++) {
            int r = bRow + i * 8;
            float4 v = *reinterpret_cast<const float4*>(Bptr + (size_t)(kt + r) * N + bCol);
            *reinterpret_cast<float4*>(&Bs[r][bCol]) = v;
        }
        __syncthreads();

#pragma unroll
        for (int kk = 0; kk < BK; kk++) {
            float a[TM], b[TN];
#pragma unroll
            for (int i = 0; i < TM; i += 4)
                *reinterpret_cast<float4*>(&a[i]) =
                    *reinterpret_cast<const float4*>(&As[kk][ty * TM + i]);
#pragma unroll
            for (int j = 0; j < TN; j += 4)
                *reinterpret_cast<float4*>(&b[j]) =
                    *reinterpret_cast<const float4*>(&Bs[kk][tx * TN + j]);
#pragma unroll
            for (int i = 0; i < TM; i++)
#pragma unroll
                for (int j = 0; j < TN; j++)
                    acc[i][j] = fmaf(a[i], b[j], acc[i][j]);
        }
        __syncthreads();
    }

#pragma unroll
    for (int i = 0; i < TM; i++) {
        int row = cRow * BM + ty * TM + i;
#pragma unroll
        for (int j = 0; j < TN; j += 4) {
            int col = cCol * BN + tx * TN + j;
            float4 v;
            v.x = acc[i][j + 0];
            v.y = acc[i][j + 1];
            v.z = acc[i][j + 2];
            v.w = acc[i][j + 3];
            if (bias) {
                v.x += bias[col + 0];
                v.y += bias[col + 1];
                v.z += bias[col + 2];
                v.w += bias[col + 3];
            }
            *reinterpret_cast<float4*>(&C[(size_t)row * N + col]) = v;
        }
    }
}

// ---------------------------------------------------------------------------
// KPConv aggregation: agg[n, p*CMID + c] = sum_k infl(n,k,p) * h[nb(n,k), c]
// One CTA per point, 128 threads (thread = channel c).
// ---------------------------------------------------------------------------
__global__ void __launch_bounds__(128)
kpconv_agg(const float* __restrict__ h, const float* __restrict__ coords,
           const int* __restrict__ neighb, const float* __restrict__ kpts,
           float* __restrict__ agg)
{
    const int n = blockIdx.x;
    const int t = threadIdx.x;

    __shared__ int   nb[KNB];
    __shared__ float rel[KNB][3];
    __shared__ float infl[KNB][PKP + 1];

    if (t < KNB) nb[t] = neighb[n * KNB + t];
    __syncthreads();
    if (t < KNB * 3) {
        int k = t / 3, d = t % 3;
        rel[k][d] = coords[(size_t)nb[k] * 3 + d] - coords[(size_t)n * 3 + d];
    }
    __syncthreads();
    for (int idx = t; idx < KNB * PKP; idx += 128) {
        int k = idx / PKP, p = idx % PKP;
        float dx = rel[k][0] - kpts[p * 3 + 0];
        float dy = rel[k][1] - kpts[p * 3 + 1];
        float dz = rel[k][2] - kpts[p * 3 + 2];
        float d  = sqrtf(dx * dx + dy * dy + dz * dz);
        infl[k][p] = fmaxf(0.0f, 1.0f - d * 1.25f);   // EXTENT = 0.8
    }
    __syncthreads();

    float acc[PKP];
#pragma unroll
    for (int p = 0; p < PKP; p++) acc[p] = 0.0f;

#pragma unroll 4
    for (int k = 0; k < KNB; k++) {
        float f = __ldg(&h[(size_t)nb[k] * CMID + t]);
#pragma unroll
        for (int p = 0; p < PKP; p++)
            acc[p] = fmaf(infl[k][p], f, acc[p]);
    }

    float* o = agg + (size_t)n * PC + t;
#pragma unroll
    for (int p = 0; p < PKP; p++) o[(size_t)p * CMID] = acc[p];
}

// ---------------------------------------------------------------------------
// BatchNorm statistics + apply
// ---------------------------------------------------------------------------
__global__ void zero_stats(float* s)
{
    s[threadIdx.x] = 0.0f;   // <<<1, 1024>>>
}

__global__ void __launch_bounds__(512)
bn_stats(const float* __restrict__ y, float* __restrict__ stats)
{
    const int c = threadIdx.x;
    const float* p = y + (size_t)blockIdx.x * 128 * COUT + c;
    float s = 0.0f, s2 = 0.0f;
    for (int r = 0; r < 128; r++) {
        float v = p[(size_t)r * COUT];
        s  += v;
        s2 = fmaf(v, v, s2);
    }
    atomicAdd(&stats[c], s);
    atomicAdd(&stats[COUT + c], s2);
}

__global__ void __launch_bounds__(256)
bn_apply(const float* __restrict__ y, const float* __restrict__ stats,
         const float* __restrict__ gamma, const float* __restrict__ beta,
         float* __restrict__ out)
{
    const int i = blockIdx.x * blockDim.x + threadIdx.x;   // 0 .. NPTS*COUT-1
    const int c = i & (COUT - 1);
    float mu  = stats[c] * (1.0f / NPTS);
    float var = stats[COUT + c] * (1.0f / NPTS) - mu * mu;
    float scale = rsqrtf(var + 1e-5f) * gamma[c];
    float v = (y[i] - mu) * scale + beta[c];
    out[i] = (v >= 0.0f) ? v : 0.1f * v;
}

__global__ void copy_coords(const float* __restrict__ a, const float* __restrict__ b,
                            float* __restrict__ out)
{
    int i = blockIdx.x * blockDim.x + threadIdx.x;
    if (i < NPTS * 3) {
        out[i]            = a[i];
        out[NPTS * 3 + i] = b[i];
    }
}

// ---------------------------------------------------------------------------
// Launcher
// ---------------------------------------------------------------------------
extern "C" void kernel_launch(void* const* d_in, const int* in_sizes, int n_in,
                              void* d_out, int out_size)
{
    (void)in_sizes; (void)n_in; (void)out_size;

    const float* W_in  = (const float*)d_in[6];
    const float* b_in  = (const float*)d_in[7];
    const float* kpts  = (const float*)d_in[8];
    const float* kpw   = (const float*)d_in[9];    // [P, Cmid, Cmid] == [1920, 128]
    const float* W_out = (const float*)d_in[10];
    const float* b_out = (const float*)d_in[11];
    const float* gamma = (const float*)d_in[12];
    const float* beta  = (const float*)d_in[13];
    float* out = (float*)d_out;

    float *h, *agg, *mid, *y, *stats;
    cudaGetSymbolAddress((void**)&h,     g_h);
    cudaGetSymbolAddress((void**)&agg,   g_agg);
    cudaGetSymbolAddress((void**)&mid,   g_mid);
    cudaGetSymbolAddress((void**)&y,     g_y);
    cudaGetSymbolAddress((void**)&stats, g_stats);

    for (int b = 0; b < 2; b++) {
        const float* x      = (const float*)d_in[0 + b];
        const float* coords = (const float*)d_in[2 + b];
        const int*   nb     = (const int*)  d_in[4 + b];
        float* out_feat = out + (size_t)b * NPTS * COUT;

        // 1x1 conv in: h = x @ W_in + b_in   [16384,256]@[256,128]
        sgemm_bias<<<dim3(CMID / 128, NPTS / 128), 256>>>(x, W_in, b_in, h, NPTS, CMID, CIN);

        // KPConv gather + influence-weighted aggregation -> agg [16384, 1920]
        kpconv_agg<<<NPTS, 128>>>(h, coords, nb, kpts, agg);

        // KP weight transform as one GEMM: mid = agg @ kpw  [16384,1920]@[1920,128]
        sgemm_bias<<<dim3(CMID / 128, NPTS / 128), 256>>>(agg, kpw, nullptr, mid, NPTS, CMID, PC);

        // 1x1 conv out: y = mid @ W_out + b_out  [16384,128]@[128,512]
        sgemm_bias<<<dim3(COUT / 128, NPTS / 128), 256>>>(mid, W_out, b_out, y, NPTS, COUT, CMID);

        // BatchNorm (two-pass) + LeakyReLU
        zero_stats<<<1, 2 * COUT>>>(stats);
        bn_stats<<<NPTS / 128, COUT>>>(y, stats);
        bn_apply<<<(NPTS * COUT) / 256, 256>>>(y, stats, gamma, beta, out_feat);
    }

    // coords pass-through
    copy_coords<<<(NPTS * 3 + 255) / 256, 256>>>(
        (const float*)d_in[2], (const float*)d_in[3], out + 2ull * NPTS * COUT);
}

// round 2
// speedup vs baseline: 1.1742x; 1.1742x over previous
#include <cuda_runtime.h>
#include <math.h>

// Problem constants
#define NPTS 16384
#define KNB  32
#define PKP  15
#define CIN  256
#define CMID 128
#define COUT 512
#define PC   (PKP * CMID)   // 1920

typedef unsigned long long ull;

// Scratch (device globals -- allocation-free). Both branches held at once.
__device__ float g_h  [2][(size_t)NPTS * CMID];     // 16 MB
__device__ float g_agg[2][(size_t)NPTS * PC];       // 252 MB
__device__ float g_mid[2][(size_t)NPTS * CMID];     // 16 MB
__device__ float g_y  [2][(size_t)NPTS * COUT];     // 64 MB
__device__ float g_stats[2][2 * COUT];

// ---------------------------------------------------------------------------
// Packed f32x2 helpers (Blackwell FFMA2 path — ptxas never auto-fuses)
// ---------------------------------------------------------------------------
__device__ __forceinline__ void fma2(ull& d, ull a, ull b)
{
    asm("fma.rn.f32x2 %0, %1, %2, %0;" : "+l"(d) : "l"(a), "l"(b));
}
__device__ __forceinline__ ull pack2(float x, float y)
{
    ull r;
    asm("mov.b64 %0, {%1, %2};" : "=l"(r) : "f"(x), "f"(y));
    return r;
}
__device__ __forceinline__ void unpack2(ull v, float& x, float& y)
{
    asm("mov.b64 {%0, %1}, %2;" : "=f"(x), "=f"(y) : "l"(v));
}

// ---------------------------------------------------------------------------
// Register-blocked SGEMM with f32x2 packed FMA, dual-branch via blockIdx.z.
// C[M,N] = A[M,K] @ B[K,N] (+ bias). BM=BN=128, BK=16, TM=TN=8, 256 thr.
// ---------------------------------------------------------------------------
__global__ void __launch_bounds__(256)
sgemm_bias2(const float* __restrict__ A0, const float* __restrict__ A1,
            const float* __restrict__ B, const float* __restrict__ bias,
            float* __restrict__ C0, float* __restrict__ C1,
            int M, int N, int K)
{
    constexpr int BM = 128, BN = 128, BK = 16, TM = 8, TN = 8;
    __shared__ __align__(16) float As[BK][BM];
    __shared__ __align__(16) float Bs[BK][BN];

    const float* A = blockIdx.z ? A1 : A0;
    float*       C = blockIdx.z ? C1 : C0;

    const int tid  = threadIdx.x;
    const int cCol = blockIdx.x;   // N tile
    const int cRow = blockIdx.y;   // M tile

    const int tx = tid % (BN / TN);   // 0..15
    const int ty = tid / (BN / TN);   // 0..15

    ull acc2[TM][TN / 2];
#pragma unroll
    for (int i = 0; i < TM; i++)
#pragma unroll
        for (int j = 0; j < TN / 2; j++) acc2[i][j] = 0ull;

    // A tile: 128x16 floats = 512 float4, 256 thr -> 2 each
    const int aRow = tid / (BK / 4);        // 0..63
    const int aCol = (tid % (BK / 4)) * 4;  // 0,4,8,12
    // B tile: 16x128 floats = 512 float4, 256 thr -> 2 each
    const int bRow = tid / (BN / 4);        // 0..7
    const int bCol = (tid % (BN / 4)) * 4;  // 0..124

    const float* Aptr = A + (size_t)cRow * BM * K;
    const float* Bptr = B + (size_t)cCol * BN;

    for (int kt = 0; kt < K; kt += BK) {
#pragma unroll
        for (int i = 0; i < 2; i++) {
            int r = aRow + i * 64;
            float4 v = *reinterpret_cast<const float4*>(Aptr + (size_t)r * K + kt + aCol);
            As[aCol + 0][r] = v.x;
            As[aCol + 1][r] = v.y;
            As[aCol + 2][r] = v.z;
            As[aCol + 3][r] = v.w;
        }
#pragma unroll
        for (int i = 0; i < 2; i++) {
            int r = bRow + i * 8;
            float4 v = *reinterpret_cast<const float4*>(Bptr + (size_t)(kt + r) * N + bCol);
            *reinterpret_cast<float4*>(&Bs[r][bCol]) = v;
        }
        __syncthreads();

#pragma unroll
        for (int kk = 0; kk < BK; kk++) {
            float a[TM];
#pragma unroll
            for (int i = 0; i < TM; i += 4)
                *reinterpret_cast<float4*>(&a[i]) =
                    *reinterpret_cast<const float4*>(&As[kk][ty * TM + i]);

            const ull* bp = reinterpret_cast<const ull*>(&Bs[kk][tx * TN]);
            ull b0 = bp[0], b1 = bp[1], b2 = bp[2], b3 = bp[3];

#pragma unroll
            for (int i = 0; i < TM; i++) {
                ull av = pack2(a[i], a[i]);
                fma2(acc2[i][0], av, b0);
                fma2(acc2[i][1], av, b1);
                fma2(acc2[i][2], av, b2);
                fma2(acc2[i][3], av, b3);
            }
        }
        __syncthreads();
    }

#pragma unroll
    for (int i = 0; i < TM; i++) {
        int row = cRow * BM + ty * TM + i;
#pragma unroll
        for (int j = 0; j < TN / 2; j += 2) {
            int col = cCol * BN + tx * TN + j * 2;
            float4 v;
            unpack2(acc2[i][j + 0], v.x, v.y);
            unpack2(acc2[i][j + 1], v.z, v.w);
            if (bias) {
                v.x += bias[col + 0];
                v.y += bias[col + 1];
                v.z += bias[col + 2];
                v.w += bias[col + 3];
            }
            *reinterpret_cast<float4*>(&C[(size_t)row * N + col]) = v;
        }
    }
}

// ---------------------------------------------------------------------------
// KPConv aggregation: agg[n, p*CMID + c] = sum_k infl(n,k,p) * h[nb(n,k), c]
// One CTA per point, 128 threads (thread = channel c). blockIdx.z = branch.
// ---------------------------------------------------------------------------
__global__ void __launch_bounds__(128)
kpconv_agg(const float* __restrict__ h0, const float* __restrict__ h1,
           const float* __restrict__ coords0, const float* __restrict__ coords1,
           const int* __restrict__ neighb0, const int* __restrict__ neighb1,
           const float* __restrict__ kpts,
           float* __restrict__ agg0, float* __restrict__ agg1)
{
    const int z = blockIdx.z;
    const float* h      = z ? h1 : h0;
    const float* coords = z ? coords1 : coords0;
    const int*   neighb = z ? neighb1 : neighb0;
    float*       agg    = z ? agg1 : agg0;

    const int n = blockIdx.x;
    const int t = threadIdx.x;

    __shared__ int   nb[KNB];
    __shared__ float rel[KNB][3];
    __shared__ float infl[KNB][PKP + 1];

    if (t < KNB) nb[t] = neighb[n * KNB + t];
    __syncthreads();
    if (t < KNB * 3) {
        int k = t / 3, d = t % 3;
        rel[k][d] = coords[(size_t)nb[k] * 3 + d] - coords[(size_t)n * 3 + d];
    }
    __syncthreads();
    for (int idx = t; idx < KNB * PKP; idx += 128) {
        int k = idx / PKP, p = idx % PKP;
        float dx = rel[k][0] - kpts[p * 3 + 0];
        float dy = rel[k][1] - kpts[p * 3 + 1];
        float dz = rel[k][2] - kpts[p * 3 + 2];
        float d  = sqrtf(dx * dx + dy * dy + dz * dz);
        infl[k][p] = fmaxf(0.0f, 1.0f - d * 1.25f);   // EXTENT = 0.8
    }
    __syncthreads();

    float acc[PKP];
#pragma unroll
    for (int p = 0; p < PKP; p++) acc[p] = 0.0f;

#pragma unroll 4
    for (int k = 0; k < KNB; k++) {
        float f = __ldg(&h[(size_t)nb[k] * CMID + t]);
#pragma unroll
        for (int p = 0; p < PKP; p++)
            acc[p] = fmaf(infl[k][p], f, acc[p]);
    }

    float* o = agg + (size_t)n * PC + t;
#pragma unroll
    for (int p = 0; p < PKP; p++) o[(size_t)p * CMID] = acc[p];
}

// ---------------------------------------------------------------------------
// BatchNorm statistics + apply (per-branch stats, batched launches)
// ---------------------------------------------------------------------------
__global__ void zero_stats(float* s)
{
    s[blockIdx.x * 1024 + threadIdx.x] = 0.0f;   // <<<2, 1024>>> covers 2*2*COUT
}

__global__ void __launch_bounds__(512)
bn_stats(const float* __restrict__ ybase, float* __restrict__ stats)
{
    const int z = blockIdx.y;
    const float* y = ybase + (size_t)z * NPTS * COUT;
    float* st = stats + (size_t)z * 2 * COUT;

    const int c = threadIdx.x;
    const float* p = y + (size_t)blockIdx.x * 128 * COUT + c;
    float s = 0.0f, s2 = 0.0f;
    for (int r = 0; r < 128; r++) {
        float v = p[(size_t)r * COUT];
        s  += v;
        s2 = fmaf(v, v, s2);
    }
    atomicAdd(&st[c], s);
    atomicAdd(&st[COUT + c], s2);
}

__global__ void __launch_bounds__(256)
bn_apply(const float* __restrict__ ybase, const float* __restrict__ stats,
         const float* __restrict__ gamma, const float* __restrict__ beta,
         float* __restrict__ outbase)
{
    const int z = blockIdx.y;
    const float* y   = ybase + (size_t)z * NPTS * COUT;
    const float* st  = stats + (size_t)z * 2 * COUT;
    float*       out = outbase + (size_t)z * NPTS * COUT;

    const int i = blockIdx.x * blockDim.x + threadIdx.x;   // 0 .. NPTS*COUT-1
    const int c = i & (COUT - 1);
    float mu  = st[c] * (1.0f / NPTS);
    float var = st[COUT + c] * (1.0f / NPTS) - mu * mu;
    float scale = rsqrtf(var + 1e-5f) * gamma[c];
    float v = (y[i] - mu) * scale + beta[c];
    out[i] = (v >= 0.0f) ? v : 0.1f * v;
}

__global__ void copy_coords(const float* __restrict__ a, const float* __restrict__ b,
                            float* __restrict__ out)
{
    int i = blockIdx.x * blockDim.x + threadIdx.x;
    if (i < NPTS * 3) {
        out[i]            = a[i];
        out[NPTS * 3 + i] = b[i];
    }
}

// ---------------------------------------------------------------------------
// Launcher
// ---------------------------------------------------------------------------
extern "C" void kernel_launch(void* const* d_in, const int* in_sizes, int n_in,
                              void* d_out, int out_size)
{
    (void)in_sizes; (void)n_in; (void)out_size;

    const float* src    = (const float*)d_in[0];
    const float* tgt    = (const float*)d_in[1];
    const float* sc     = (const float*)d_in[2];
    const float* tc     = (const float*)d_in[3];
    const int*   snb    = (const int*)  d_in[4];
    const int*   tnb    = (const int*)  d_in[5];
    const float* W_in   = (const float*)d_in[6];
    const float* b_in   = (const float*)d_in[7];
    const float* kpts   = (const float*)d_in[8];
    const float* kpw    = (const float*)d_in[9];    // [P, Cmid, Cmid] == [1920, 128]
    const float* W_out  = (const float*)d_in[10];
    const float* b_out  = (const float*)d_in[11];
    const float* gamma  = (const float*)d_in[12];
    const float* beta   = (const float*)d_in[13];
    float* out = (float*)d_out;

    float *h, *agg, *mid, *y, *stats;
    cudaGetSymbolAddress((void**)&h,     g_h);
    cudaGetSymbolAddress((void**)&agg,   g_agg);
    cudaGetSymbolAddress((void**)&mid,   g_mid);
    cudaGetSymbolAddress((void**)&y,     g_y);
    cudaGetSymbolAddress((void**)&stats, g_stats);

    float* h0   = h;                        float* h1   = h   + (size_t)NPTS * CMID;
    float* agg0 = agg;                      float* agg1 = agg + (size_t)NPTS * PC;
    float* mid0 = mid;                      float* mid1 = mid + (size_t)NPTS * CMID;

    // 1x1 conv in: h = x @ W_in + b_in   [16384,256]@[256,128], both branches
    sgemm_bias2<<<dim3(1, NPTS / 128, 2), 256>>>(src, tgt, W_in, b_in,
                                                 h0, h1, NPTS, CMID, CIN);

    // KPConv gather + influence-weighted aggregation -> agg [16384, 1920] x2
    kpconv_agg<<<dim3(NPTS, 1, 2), 128>>>(h0, h1, sc, tc, snb, tnb, kpts, agg0, agg1);

    // KP weight transform as one GEMM: mid = agg @ kpw  [16384,1920]@[1920,128]
    sgemm_bias2<<<dim3(1, NPTS / 128, 2), 256>>>(agg0, agg1, kpw, nullptr,
                                                 mid0, mid1, NPTS, CMID, PC);

    // 1x1 conv out: y = mid @ W_out + b_out  [16384,128]@[128,512]
    sgemm_bias2<<<dim3(COUT / 128, NPTS / 128, 2), 256>>>(mid0, mid1, W_out, b_out,
                                                          y, y + (size_t)NPTS * COUT,
                                                          NPTS, COUT, CMID);

    // BatchNorm (two-pass) + LeakyReLU, both branches
    zero_stats<<<2, 1024>>>(stats);
    bn_stats<<<dim3(NPTS / 128, 2), COUT>>>(y, stats);
    bn_apply<<<dim3((NPTS * COUT) / 256, 2), 256>>>(y, stats, gamma, beta, out);

    // coords pass-through
    copy_coords<<<(NPTS * 3 + 255) / 256, 256>>>(sc, tc, out + 2ull * NPTS * COUT);
}

// round 4
// speedup vs baseline: 1.9252x; 1.6397x over previous
#include <cuda_runtime.h>
#include <cuda_bf16.h>
#include <math.h>
#include <stdint.h>

#define NPTS 16384
#define KNB  32
#define PKP  15
#define CIN  256
#define CMID 128
#define COUT 512
#define PC   (PKP * CMID)   // 1920

typedef unsigned long long ull;
typedef __nv_bfloat16 bf16;

// ---------------------------------------------------------------------------
// Scratch (device globals -- allocation-free). bf16 hi/lo split operands.
// ---------------------------------------------------------------------------
__device__ __align__(128) bf16 g_xs_h[2ull * NPTS * CIN],  g_xs_l[2ull * NPTS * CIN];
__device__ __align__(128) bf16 g_h_h [2ull * NPTS * CMID], g_h_l [2ull * NPTS * CMID];
__device__ __align__(128) bf16 g_ag_h[2ull * NPTS * PC],   g_ag_l[2ull * NPTS * PC];
__device__ __align__(128) bf16 g_md_h[2ull * NPTS * CMID], g_md_l[2ull * NPTS * CMID];
__device__ __align__(128) float g_y  [2ull * NPTS * COUT];
__device__ __align__(128) bf16 g_wi_h[CIN * CMID],  g_wi_l[CIN * CMID];    // [K,N]
__device__ __align__(128) bf16 g_kw_h[PC * CMID],   g_kw_l[PC * CMID];     // [K,N]
__device__ __align__(128) bf16 g_wo_h[CMID * COUT], g_wo_l[CMID * COUT];   // [K,N]
__device__ float g_stats[2 * 2 * COUT];

// ---------------------------------------------------------------------------
// PTX helpers (all arch-portable: sm_80+ features, legal on compute_103)
// ---------------------------------------------------------------------------
__device__ __forceinline__ uint32_t s2u(const void* p)
{
    return (uint32_t)__cvta_generic_to_shared(p);
}
__device__ __forceinline__ void cpa16(uint32_t s, const void* g)
{
    asm volatile("cp.async.cg.shared.global [%0], [%1], 16;" :: "r"(s), "l"(g));
}
__device__ __forceinline__ void cp_commit()
{
    asm volatile("cp.async.commit_group;" ::: "memory");
}
template <int N>
__device__ __forceinline__ void cp_wait()
{
    asm volatile("cp.async.wait_group %0;" :: "n"(N) : "memory");
}
__device__ __forceinline__ void ldsm4(uint32_t* r, uint32_t a)
{
    asm volatile("ldmatrix.sync.aligned.m8n8.x4.shared.b16 {%0,%1,%2,%3}, [%4];"
                 : "=r"(r[0]), "=r"(r[1]), "=r"(r[2]), "=r"(r[3]) : "r"(a));
}
__device__ __forceinline__ void ldsm4t(uint32_t* r, uint32_t a)
{
    asm volatile("ldmatrix.sync.aligned.m8n8.x4.trans.shared.b16 {%0,%1,%2,%3}, [%4];"
                 : "=r"(r[0]), "=r"(r[1]), "=r"(r[2]), "=r"(r[3]) : "r"(a));
}
__device__ __forceinline__ void mma16816(float* c, const uint32_t* a, const uint32_t* b)
{
    asm volatile(
        "mma.sync.aligned.m16n8k16.row.col.f32.bf16.bf16.f32 "
        "{%0,%1,%2,%3}, {%4,%5,%6,%7}, {%8,%9}, {%0,%1,%2,%3};"
        : "+f"(c[0]), "+f"(c[1]), "+f"(c[2]), "+f"(c[3])
        : "r"(a[0]), "r"(a[1]), "r"(a[2]), "r"(a[3]), "r"(b[0]), "r"(b[1]));
}
__device__ __forceinline__ void split_f32(float v, bf16& h, bf16& l)
{
    h = __float2bfloat16(v);
    l = __float2bfloat16(v - __bfloat162float(h));
}

// ---------------------------------------------------------------------------
// HMMA GEMM, bf16x3 split emulation of fp32, cp.async double-buffered.
// C[16384, Ntot] = A[16384, K] @ B[K, Ntot]  (+bias)
// CTA tile 128x128, BK=64, 8 warps (2m x 4n), warp tile 64x32.
// Stage layout (64KB): Ah[16K] Al[16K] Bh[16K] Bl[16K]; 2 stages = 128KB.
// MODE 0: C -> bf16 hi/lo split arrays. MODE 1: C -> fp32 (+bias).
// blockIdx = (nTile, mTile, branch)
// ---------------------------------------------------------------------------
#define STAGE_BYTES 65536

__device__ __forceinline__ void issue_chunk(
    const bf16* gAh, const bf16* gAl, const bf16* gBh, const bf16* gBl,
    int K, int Ntot, int c, uint32_t sb, int tid)
{
    const int kt = c * 64;
#pragma unroll
    for (int i = 0; i < 4; i++) {
        int idx = tid + i * 256;            // 1024 16B-chunks: A is 128r x 8ch
        int r = idx >> 3, ch = idx & 7;
        uint32_t off = (uint32_t)(r * 128 + ((ch ^ (r & 7)) << 4));
        size_t go = (size_t)r * K + kt + ch * 8;
        cpa16(sb + off,         gAh + go);
        cpa16(sb + 16384 + off, gAl + go);
    }
#pragma unroll
    for (int i = 0; i < 4; i++) {
        int idx = tid + i * 256;            // B is 64r x 16ch
        int r = idx >> 4, ch = idx & 15;
        uint32_t off = (uint32_t)(r * 256 + ((ch ^ (r & 7)) << 4));
        size_t go = (size_t)(kt + r) * Ntot + ch * 8;
        cpa16(sb + 32768 + off, gBh + go);
        cpa16(sb + 49152 + off, gBl + go);
    }
    cp_commit();
}

template <int MODE>
__global__ void __launch_bounds__(256)
mma_gemm(const bf16* __restrict__ Ah, const bf16* __restrict__ Al,
         const bf16* __restrict__ Bh, const bf16* __restrict__ Bl,
         const float* __restrict__ bias,
         float* __restrict__ Cf, bf16* __restrict__ Ch, bf16* __restrict__ Cl,
         int K, int Ntot)
{
    extern __shared__ char smem[];
    const uint32_t sb0 = s2u(smem);

    const int tid  = threadIdx.x;
    const int wid  = tid >> 5;
    const int lane = tid & 31;
    const int z     = blockIdx.z;
    const int mTile = blockIdx.y;
    const int nTile = blockIdx.x;

    const int m0 = (wid & 1) * 64;     // warp m offset within 128
    const int n0 = (wid >> 1) * 32;    // warp n offset within 128

    const size_t brA = (size_t)z * NPTS * K;
    const size_t brC = (size_t)z * NPTS * Ntot;
    const bf16* gAh = Ah + brA + (size_t)mTile * 128 * K;
    const bf16* gAl = Al + brA + (size_t)mTile * 128 * K;
    const bf16* gBh = Bh + (size_t)nTile * 128;
    const bf16* gBl = Bl + (size_t)nTile * 128;

    float acc[4][4][4];
#pragma unroll
    for (int i = 0; i < 4; i++)
#pragma unroll
        for (int j = 0; j < 4; j++)
#pragma unroll
            for (int t = 0; t < 4; t++) acc[i][j][t] = 0.0f;

    const int nch = K >> 6;
    issue_chunk(gAh, gAl, gBh, gBl, K, Ntot, 0, sb0, tid);

    for (int c = 0; c < nch; c++) {
        if (c + 1 < nch) {
            issue_chunk(gAh, gAl, gBh, gBl, K, Ntot, c + 1,
                        sb0 + ((c + 1) & 1) * STAGE_BYTES, tid);
            cp_wait<1>();
        } else {
            cp_wait<0>();
        }
        __syncthreads();

        const uint32_t sb = sb0 + (c & 1) * STAGE_BYTES;
        const uint32_t sA = sb, sB = sb + 32768;

#pragma unroll
        for (int ks = 0; ks < 4; ks++) {
            // B fragments: 4 n8 tiles, hi+lo (two ldmatrix.x4.trans each)
            uint32_t bh[4][2], bl[4][2];
#pragma unroll
            for (int pr = 0; pr < 2; pr++) {
                int k   = ks * 16 + (lane & 15);
                int chn = ((n0 + pr * 16) >> 3) + (lane >> 4);
                uint32_t ba = sB + (uint32_t)(k * 256 + ((chn ^ (k & 7)) << 4));
                uint32_t t[4];
                ldsm4t(t, ba);
                bh[pr * 2][0] = t[0]; bh[pr * 2][1] = t[1];
                bh[pr * 2 + 1][0] = t[2]; bh[pr * 2 + 1][1] = t[3];
                ldsm4t(t, ba + 16384);
                bl[pr * 2][0] = t[0]; bl[pr * 2][1] = t[1];
                bl[pr * 2 + 1][0] = t[2]; bl[pr * 2 + 1][1] = t[3];
            }
#pragma unroll
            for (int mf = 0; mf < 4; mf++) {
                int r   = m0 + mf * 16 + (lane & 15);
                int chk = ks * 2 + (lane >> 4);
                uint32_t aa = sA + (uint32_t)(r * 128 + ((chk ^ (r & 7)) << 4));
                uint32_t ah[4], al[4];
                ldsm4(ah, aa);
                ldsm4(al, aa + 16384);
#pragma unroll
                for (int nf = 0; nf < 4; nf++) {
                    mma16816(acc[mf][nf], ah, bh[nf]);
                    mma16816(acc[mf][nf], ah, bl[nf]);
                    mma16816(acc[mf][nf], al, bh[nf]);
                }
            }
        }
        __syncthreads();
    }

    // Epilogue: c0,c1 -> (row g, col 2t, 2t+1); c2,c3 -> (row g+8, ...)
    const int g  = lane >> 2;
    const int tg = lane & 3;
#pragma unroll
    for (int mf = 0; mf < 4; mf++) {
#pragma unroll
        for (int nf = 0; nf < 4; nf++) {
            int col = nTile * 128 + n0 + nf * 8 + tg * 2;
            float b0 = bias ? bias[col] : 0.0f;
            float b1 = bias ? bias[col + 1] : 0.0f;
#pragma unroll
            for (int hrow = 0; hrow < 2; hrow++) {
                int row = mTile * 128 + m0 + mf * 16 + g + hrow * 8;
                float v0 = acc[mf][nf][hrow * 2 + 0] + b0;
                float v1 = acc[mf][nf][hrow * 2 + 1] + b1;
                size_t o = brC + (size_t)row * Ntot + col;
                if (MODE == 1) {
                    *reinterpret_cast<float2*>(Cf + o) = make_float2(v0, v1);
                } else {
                    bf16 h0, l0, h1, l1;
                    split_f32(v0, h0, l0);
                    split_f32(v1, h1, l1);
                    __nv_bfloat162 hp; hp.x = h0; hp.y = h1;
                    __nv_bfloat162 lp; lp.x = l0; lp.y = l1;
                    *reinterpret_cast<__nv_bfloat162*>(Ch + o) = hp;
                    *reinterpret_cast<__nv_bfloat162*>(Cl + o) = lp;
                }
            }
        }
    }
}

// ---------------------------------------------------------------------------
// fp32 -> bf16 hi/lo split (activations, both branches; weights single)
// ---------------------------------------------------------------------------
__global__ void __launch_bounds__(256)
split_act(const float* __restrict__ a0, const float* __restrict__ a1,
          bf16* __restrict__ oh, bf16* __restrict__ ol, int n)
{
    const int z = blockIdx.y;
    const float* a = z ? a1 : a0;
    const size_t off = (size_t)z * n;
    int i = blockIdx.x * 256 + threadIdx.x;
    if (i < n) {
        bf16 h, l;
        split_f32(a[i], h, l);
        oh[off + i] = h;
        ol[off + i] = l;
    }
}

__global__ void __launch_bounds__(256)
split_w(const float* __restrict__ in, bf16* __restrict__ oh, bf16* __restrict__ ol, int n)
{
    int i = blockIdx.x * 256 + threadIdx.x;
    if (i < n) {
        bf16 h, l;
        split_f32(in[i], h, l);
        oh[i] = h;
        ol[i] = l;
    }
}

// ---------------------------------------------------------------------------
// KPConv aggregation: agg[n, p*CMID + c] = sum_k infl(n,k,p) * h[nb(n,k), c]
// ---------------------------------------------------------------------------
__global__ void __launch_bounds__(128)
kpconv_agg(const bf16* __restrict__ hh, const bf16* __restrict__ hl,
           const float* __restrict__ coords0, const float* __restrict__ coords1,
           const int* __restrict__ neighb0, const int* __restrict__ neighb1,
           const float* __restrict__ kpts,
           bf16* __restrict__ aggh, bf16* __restrict__ aggl)
{
    const int z = blockIdx.z;
    const float* coords = z ? coords1 : coords0;
    const int*   neighb = z ? neighb1 : neighb0;
    const size_t brH = (size_t)z * NPTS * CMID;
    const size_t brA = (size_t)z * NPTS * PC;

    const int n = blockIdx.x;
    const int t = threadIdx.x;

    __shared__ int   nb[KNB];
    __shared__ float rel[KNB][3];
    __shared__ float infl[KNB][PKP + 1];

    if (t < KNB) nb[t] = neighb[n * KNB + t];
    __syncthreads();
    if (t < KNB * 3) {
        int k = t / 3, d = t % 3;
        rel[k][d] = coords[(size_t)nb[k] * 3 + d] - coords[(size_t)n * 3 + d];
    }
    __syncthreads();
    for (int idx = t; idx < KNB * PKP; idx += 128) {
        int k = idx / PKP, p = idx % PKP;
        float dx = rel[k][0] - kpts[p * 3 + 0];
        float dy = rel[k][1] - kpts[p * 3 + 1];
        float dz = rel[k][2] - kpts[p * 3 + 2];
        float d  = sqrtf(dx * dx + dy * dy + dz * dz);
        infl[k][p] = fmaxf(0.0f, 1.0f - d * 1.25f);   // EXTENT = 0.8
    }
    __syncthreads();

    float acc[PKP];
#pragma unroll
    for (int p = 0; p < PKP; p++) acc[p] = 0.0f;

#pragma unroll 4
    for (int k = 0; k < KNB; k++) {
        size_t idx = brH + (size_t)nb[k] * CMID + t;
        float f = __bfloat162float(__ldg(&hh[idx])) + __bfloat162float(__ldg(&hl[idx]));
#pragma unroll
        for (int p = 0; p < PKP; p++)
            acc[p] = fmaf(infl[k][p], f, acc[p]);
    }

#pragma unroll
    for (int p = 0; p < PKP; p++) {
        size_t o = brA + (size_t)n * PC + (size_t)p * CMID + t;
        bf16 h, l;
        split_f32(acc[p], h, l);
        aggh[o] = h;
        aggl[o] = l;
    }
}

// ---------------------------------------------------------------------------
// BatchNorm statistics + apply
// ---------------------------------------------------------------------------
__global__ void zero_stats(float* s)
{
    s[blockIdx.x * 1024 + threadIdx.x] = 0.0f;   // <<<2, 1024>>>
}

__global__ void __launch_bounds__(512)
bn_stats(const float* __restrict__ ybase, float* __restrict__ stats)
{
    const int z = blockIdx.y;
    const float* y = ybase + (size_t)z * NPTS * COUT;
    float* st = stats + (size_t)z * 2 * COUT;

    const int c = threadIdx.x;
    const float* p = y + (size_t)blockIdx.x * 128 * COUT + c;
    float s = 0.0f, s2 = 0.0f;
    for (int r = 0; r < 128; r++) {
        float v = p[(size_t)r * COUT];
        s  += v;
        s2 = fmaf(v, v, s2);
    }
    atomicAdd(&st[c], s);
    atomicAdd(&st[COUT + c], s2);
}

__global__ void __launch_bounds__(256)
bn_apply(const float* __restrict__ ybase, const float* __restrict__ stats,
         const float* __restrict__ gamma, const float* __restrict__ beta,
         float* __restrict__ outbase)
{
    const int z = blockIdx.y;
    const float* y   = ybase + (size_t)z * NPTS * COUT;
    const float* st  = stats + (size_t)z * 2 * COUT;
    float*       out = outbase + (size_t)z * NPTS * COUT;

    const int i = blockIdx.x * blockDim.x + threadIdx.x;
    const int c = i & (COUT - 1);
    float mu  = st[c] * (1.0f / NPTS);
    float var = st[COUT + c] * (1.0f / NPTS) - mu * mu;
    float scale = rsqrtf(var + 1e-5f) * gamma[c];
    float v = (y[i] - mu) * scale + beta[c];
    out[i] = (v >= 0.0f) ? v : 0.1f * v;
}

__global__ void copy_coords(const float* __restrict__ a, const float* __restrict__ b,
                            float* __restrict__ out)
{
    int i = blockIdx.x * blockDim.x + threadIdx.x;
    if (i < NPTS * 3) {
        out[i]            = a[i];
        out[NPTS * 3 + i] = b[i];
    }
}

// ---------------------------------------------------------------------------
// Launcher
// ---------------------------------------------------------------------------
#define SMEM_DYN (2 * STAGE_BYTES)

extern "C" void kernel_launch(void* const* d_in, const int* in_sizes, int n_in,
                              void* d_out, int out_size)
{
    (void)in_sizes; (void)n_in; (void)out_size;

    const float* src    = (const float*)d_in[0];
    const float* tgt    = (const float*)d_in[1];
    const float* sc     = (const float*)d_in[2];
    const float* tc     = (const float*)d_in[3];
    const int*   snb    = (const int*)  d_in[4];
    const int*   tnb    = (const int*)  d_in[5];
    const float* W_in   = (const float*)d_in[6];
    const float* b_in   = (const float*)d_in[7];
    const float* kpts   = (const float*)d_in[8];
    const float* kpw    = (const float*)d_in[9];    // [1920, 128] = [K, N]
    const float* W_out  = (const float*)d_in[10];
    const float* b_out  = (const float*)d_in[11];
    const float* gamma  = (const float*)d_in[12];
    const float* beta   = (const float*)d_in[13];
    float* out = (float*)d_out;

    bf16 *xs_h, *xs_l, *h_h, *h_l, *ag_h, *ag_l, *md_h, *md_l;
    bf16 *wi_h, *wi_l, *kw_h, *kw_l, *wo_h, *wo_l;
    float *y, *stats;
    cudaGetSymbolAddress((void**)&xs_h, g_xs_h);  cudaGetSymbolAddress((void**)&xs_l, g_xs_l);
    cudaGetSymbolAddress((void**)&h_h,  g_h_h);   cudaGetSymbolAddress((void**)&h_l,  g_h_l);
    cudaGetSymbolAddress((void**)&ag_h, g_ag_h);  cudaGetSymbolAddress((void**)&ag_l, g_ag_l);
    cudaGetSymbolAddress((void**)&md_h, g_md_h);  cudaGetSymbolAddress((void**)&md_l, g_md_l);
    cudaGetSymbolAddress((void**)&wi_h, g_wi_h);  cudaGetSymbolAddress((void**)&wi_l, g_wi_l);
    cudaGetSymbolAddress((void**)&kw_h, g_kw_h);  cudaGetSymbolAddress((void**)&kw_l, g_kw_l);
    cudaGetSymbolAddress((void**)&wo_h, g_wo_h);  cudaGetSymbolAddress((void**)&wo_l, g_wo_l);
    cudaGetSymbolAddress((void**)&y, g_y);
    cudaGetSymbolAddress((void**)&stats, g_stats);

    cudaFuncSetAttribute(mma_gemm<0>, cudaFuncAttributeMaxDynamicSharedMemorySize, SMEM_DYN);
    cudaFuncSetAttribute(mma_gemm<1>, cudaFuncAttributeMaxDynamicSharedMemorySize, SMEM_DYN);

    // Weight splits (no transpose needed: weights already [K, N])
    split_w<<<(CIN * CMID + 255) / 256, 256>>>(W_in, wi_h, wi_l, CIN * CMID);
    split_w<<<(PC * CMID + 255) / 256, 256>>>(kpw, kw_h, kw_l, PC * CMID);
    split_w<<<(CMID * COUT + 255) / 256, 256>>>(W_out, wo_h, wo_l, CMID * COUT);

    // Split input activations (both branches)
    split_act<<<dim3((NPTS * CIN + 255) / 256, 2), 256>>>(src, tgt, xs_h, xs_l, NPTS * CIN);

    // GEMM1: h = x @ W_in + b_in   [16384,256]@[256,128] -> split bf16
    mma_gemm<0><<<dim3(1, NPTS / 128, 2), 256, SMEM_DYN>>>(
        xs_h, xs_l, wi_h, wi_l, b_in, nullptr, h_h, h_l, CIN, CMID);

    // KPConv gather + aggregation -> agg split bf16 [16384, 1920]
    kpconv_agg<<<dim3(NPTS, 1, 2), 128>>>(h_h, h_l, sc, tc, snb, tnb, kpts, ag_h, ag_l);

    // mid = agg @ kpw  [16384,1920]@[1920,128] -> split bf16
    mma_gemm<0><<<dim3(1, NPTS / 128, 2), 256, SMEM_DYN>>>(
        ag_h, ag_l, kw_h, kw_l, nullptr, nullptr, md_h, md_l, PC, CMID);

    // y = mid @ W_out + b_out  [16384,128]@[128,512] -> fp32
    mma_gemm<1><<<dim3(COUT / 128, NPTS / 128, 2), 256, SMEM_DYN>>>(
        md_h, md_l, wo_h, wo_l, b_out, y, nullptr, nullptr, CMID, COUT);

    // BatchNorm (two-pass) + LeakyReLU, both branches
    zero_stats<<<2, 1024>>>(stats);
    bn_stats<<<dim3(NPTS / 128, 2), COUT>>>(y, stats);
    bn_apply<<<dim3((NPTS * COUT) / 256, 2), 256>>>(y, stats, gamma, beta, out);

    // coords pass-through
    copy_coords<<<(NPTS * 3 + 255) / 256, 256>>>(sc, tc, out + 2ull * NPTS * COUT);
}

// round 5
// speedup vs baseline: 2.0637x; 1.0719x over previous
#include <cuda_runtime.h>
#include <cuda_bf16.h>
#include <math.h>
#include <stdint.h>

#define NPTS 16384
#define KNB  32
#define PKP  15
#define CIN  256
#define CMID 128
#define COUT 512
#define PC   (PKP * CMID)   // 1920

typedef unsigned long long ull;
typedef __nv_bfloat16 bf16;
typedef __nv_bfloat162 bf162;

// ---------------------------------------------------------------------------
// Scratch (device globals -- allocation-free)
// ---------------------------------------------------------------------------
__device__ __align__(128) bf16  g_xs_h[2ull * NPTS * CIN],  g_xs_l[2ull * NPTS * CIN];
__device__ __align__(128) bf162 g_h_il[2ull * NPTS * CMID];                 // (hi,lo) pairs
__device__ __align__(128) bf16  g_ag_h[2ull * NPTS * PC],   g_ag_l[2ull * NPTS * PC];
__device__ __align__(128) bf16  g_md_h[2ull * NPTS * CMID], g_md_l[2ull * NPTS * CMID];
__device__ __align__(128) float g_y  [2ull * NPTS * COUT];
__device__ __align__(128) bf16  g_wi_h[CIN * CMID],  g_wi_l[CIN * CMID];    // [K,N]
__device__ __align__(128) bf16  g_kw_h[PC * CMID],   g_kw_l[PC * CMID];     // [K,N]
__device__ __align__(128) bf16  g_wo_h[CMID * COUT], g_wo_l[CMID * COUT];   // [K,N]
__device__ float g_stats[2 * 2 * COUT];

// ---------------------------------------------------------------------------
// PTX helpers (sm_80+ portable, legal on compute_103)
// ---------------------------------------------------------------------------
__device__ __forceinline__ uint32_t s2u(const void* p)
{
    return (uint32_t)__cvta_generic_to_shared(p);
}
__device__ __forceinline__ void cpa16(uint32_t s, const void* g)
{
    asm volatile("cp.async.cg.shared.global [%0], [%1], 16;" :: "r"(s), "l"(g));
}
__device__ __forceinline__ void cp_commit()
{
    asm volatile("cp.async.commit_group;" ::: "memory");
}
template <int N>
__device__ __forceinline__ void cp_wait()
{
    asm volatile("cp.async.wait_group %0;" :: "n"(N) : "memory");
}
__device__ __forceinline__ void ldsm4(uint32_t* r, uint32_t a)
{
    asm volatile("ldmatrix.sync.aligned.m8n8.x4.shared.b16 {%0,%1,%2,%3}, [%4];"
                 : "=r"(r[0]), "=r"(r[1]), "=r"(r[2]), "=r"(r[3]) : "r"(a));
}
__device__ __forceinline__ void ldsm4t(uint32_t* r, uint32_t a)
{
    asm volatile("ldmatrix.sync.aligned.m8n8.x4.trans.shared.b16 {%0,%1,%2,%3}, [%4];"
                 : "=r"(r[0]), "=r"(r[1]), "=r"(r[2]), "=r"(r[3]) : "r"(a));
}
__device__ __forceinline__ void mma16816(float* c, const uint32_t* a, const uint32_t* b)
{
    asm volatile(
        "mma.sync.aligned.m16n8k16.row.col.f32.bf16.bf16.f32 "
        "{%0,%1,%2,%3}, {%4,%5,%6,%7}, {%8,%9}, {%0,%1,%2,%3};"
        : "+f"(c[0]), "+f"(c[1]), "+f"(c[2]), "+f"(c[3])
        : "r"(a[0]), "r"(a[1]), "r"(a[2]), "r"(a[3]), "r"(b[0]), "r"(b[1]));
}
__device__ __forceinline__ void split_f32(float v, bf16& h, bf16& l)
{
    h = __float2bfloat16(v);
    l = __float2bfloat16(v - __bfloat162float(h));
}

// ---------------------------------------------------------------------------
// HMMA GEMM, bf16x3 split emulation of fp32, 3-stage cp.async pipeline.
// C[16384, Ntot] = A[16384, K] @ B[K, Ntot] (+bias)
// CTA tile 128x128, BK=64, 8 warps (2m x 4n), warp tile 64x32.
// Stage (64KB): Ah[16K] Al[16K] Bh[16K] Bl[16K]; 3 stages = 192KB.
// MODE 0: C -> bf16 hi/lo split arrays.
// MODE 2: C -> interleaved (hi,lo) bf162 array (+bias).
// MODE 3: C -> fp32 (+bias) AND per-channel BN stats via atomics.
// blockIdx = (nTile, mTile, branch)
// ---------------------------------------------------------------------------
#define STAGE_BYTES 65536

__device__ __forceinline__ void issue_chunk(
    const bf16* gAh, const bf16* gAl, const bf16* gBh, const bf16* gBl,
    int K, int Ntot, int c, uint32_t sb, int tid)
{
    const int kt = c * 64;
#pragma unroll
    for (int i = 0; i < 4; i++) {
        int idx = tid + i * 256;            // A: 128 rows x 8 16B-chunks
        int r = idx >> 3, ch = idx & 7;
        uint32_t off = (uint32_t)(r * 128 + ((ch ^ (r & 7)) << 4));
        size_t go = (size_t)r * K + kt + ch * 8;
        cpa16(sb + off,         gAh + go);
        cpa16(sb + 16384 + off, gAl + go);
    }
#pragma unroll
    for (int i = 0; i < 4; i++) {
        int idx = tid + i * 256;            // B: 64 rows x 16 16B-chunks
        int r = idx >> 4, ch = idx & 15;
        uint32_t off = (uint32_t)(r * 256 + ((ch ^ (r & 7)) << 4));
        size_t go = (size_t)(kt + r) * Ntot + ch * 8;
        cpa16(sb + 32768 + off, gBh + go);
        cpa16(sb + 49152 + off, gBl + go);
    }
    cp_commit();
}

template <int MODE>
__global__ void __launch_bounds__(256)
mma_gemm(const bf16* __restrict__ Ah, const bf16* __restrict__ Al,
         const bf16* __restrict__ Bh, const bf16* __restrict__ Bl,
         const float* __restrict__ bias,
         float* __restrict__ Cf, bf16* __restrict__ Ch, bf16* __restrict__ Cl,
         bf162* __restrict__ Cil, float* __restrict__ stats,
         int K, int Ntot)
{
    extern __shared__ char smem[];
    const uint32_t sb0 = s2u(smem);

    const int tid  = threadIdx.x;
    const int wid  = tid >> 5;
    const int lane = tid & 31;
    const int z     = blockIdx.z;
    const int mTile = blockIdx.y;
    const int nTile = blockIdx.x;

    const int m0 = (wid & 1) * 64;     // warp m offset within 128
    const int n0 = (wid >> 1) * 32;    // warp n offset within 128

    const size_t brA = (size_t)z * NPTS * K;
    const size_t brC = (size_t)z * NPTS * Ntot;
    const bf16* gAh = Ah + brA + (size_t)mTile * 128 * K;
    const bf16* gAl = Al + brA + (size_t)mTile * 128 * K;
    const bf16* gBh = Bh + (size_t)nTile * 128;
    const bf16* gBl = Bl + (size_t)nTile * 128;

    float acc[4][4][4];
#pragma unroll
    for (int i = 0; i < 4; i++)
#pragma unroll
        for (int j = 0; j < 4; j++)
#pragma unroll
            for (int t = 0; t < 4; t++) acc[i][j][t] = 0.0f;

    const int nch = K >> 6;
    issue_chunk(gAh, gAl, gBh, gBl, K, Ntot, 0, sb0, tid);
    if (nch > 1)
        issue_chunk(gAh, gAl, gBh, gBl, K, Ntot, 1, sb0 + STAGE_BYTES, tid);
    else
        cp_commit();

    int bufn = 2 % 3;
    for (int c = 0; c < nch; c++) {
        if (c + 2 < nch)
            issue_chunk(gAh, gAl, gBh, gBl, K, Ntot, c + 2,
                        sb0 + bufn * STAGE_BYTES, tid);
        else
            cp_commit();   // empty group keeps wait count aligned
        bufn = (bufn + 1) % 3;
        cp_wait<2>();
        __syncthreads();

        const uint32_t sb = sb0 + (c % 3) * STAGE_BYTES;
        const uint32_t sA = sb, sB = sb + 32768;

#pragma unroll
        for (int ks = 0; ks < 4; ks++) {
            uint32_t bh[4][2], bl[4][2];
#pragma unroll
            for (int pr = 0; pr < 2; pr++) {
                int k   = ks * 16 + (lane & 15);
                int chn = ((n0 + pr * 16) >> 3) + (lane >> 4);
                uint32_t ba = sB + (uint32_t)(k * 256 + ((chn ^ (k & 7)) << 4));
                uint32_t t[4];
                ldsm4t(t, ba);
                bh[pr * 2][0] = t[0]; bh[pr * 2][1] = t[1];
                bh[pr * 2 + 1][0] = t[2]; bh[pr * 2 + 1][1] = t[3];
                ldsm4t(t, ba + 16384);
                bl[pr * 2][0] = t[0]; bl[pr * 2][1] = t[1];
                bl[pr * 2 + 1][0] = t[2]; bl[pr * 2 + 1][1] = t[3];
            }
#pragma unroll
            for (int mf = 0; mf < 4; mf++) {
                int r   = m0 + mf * 16 + (lane & 15);
                int chk = ks * 2 + (lane >> 4);
                uint32_t aa = sA + (uint32_t)(r * 128 + ((chk ^ (r & 7)) << 4));
                uint32_t ah[4], al[4];
                ldsm4(ah, aa);
                ldsm4(al, aa + 16384);
#pragma unroll
                for (int nf = 0; nf < 4; nf++) {
                    mma16816(acc[mf][nf], ah, bh[nf]);
                    mma16816(acc[mf][nf], ah, bl[nf]);
                    mma16816(acc[mf][nf], al, bh[nf]);
                }
            }
        }
        __syncthreads();
    }

    // Epilogue. acc[mf][nf]: c0,c1 -> (row g, col 2tg, 2tg+1); c2,c3 -> row g+8.
    const int g  = lane >> 2;
    const int tg = lane & 3;

    float ts[4][2], tq[4][2];   // BN partial sums per nf per col-in-pair
    if (MODE == 3) {
#pragma unroll
        for (int nf = 0; nf < 4; nf++)
            ts[nf][0] = ts[nf][1] = tq[nf][0] = tq[nf][1] = 0.0f;
    }

#pragma unroll
    for (int mf = 0; mf < 4; mf++) {
#pragma unroll
        for (int nf = 0; nf < 4; nf++) {
            int col = nTile * 128 + n0 + nf * 8 + tg * 2;
            float b0 = bias ? bias[col] : 0.0f;
            float b1 = bias ? bias[col + 1] : 0.0f;
#pragma unroll
            for (int hrow = 0; hrow < 2; hrow++) {
                int row = mTile * 128 + m0 + mf * 16 + g + hrow * 8;
                float v0 = acc[mf][nf][hrow * 2 + 0] + b0;
                float v1 = acc[mf][nf][hrow * 2 + 1] + b1;
                size_t o = brC + (size_t)row * Ntot + col;
                if (MODE == 3) {
                    *reinterpret_cast<float2*>(Cf + o) = make_float2(v0, v1);
                    ts[nf][0] += v0;           tq[nf][0] = fmaf(v0, v0, tq[nf][0]);
                    ts[nf][1] += v1;           tq[nf][1] = fmaf(v1, v1, tq[nf][1]);
                } else if (MODE == 2) {
                    bf16 h0, l0, h1, l1;
                    split_f32(v0, h0, l0);
                    split_f32(v1, h1, l1);
                    bf162 p0; p0.x = h0; p0.y = l0;
                    bf162 p1; p1.x = h1; p1.y = l1;
                    uint2 pk;
                    pk.x = *reinterpret_cast<uint32_t*>(&p0);
                    pk.y = *reinterpret_cast<uint32_t*>(&p1);
                    *reinterpret_cast<uint2*>(Cil + o) = pk;
                } else {
                    bf16 h0, l0, h1, l1;
                    split_f32(v0, h0, l0);
                    split_f32(v1, h1, l1);
                    bf162 hp; hp.x = h0; hp.y = h1;
                    bf162 lp; lp.x = l0; lp.y = l1;
                    *reinterpret_cast<bf162*>(Ch + o) = hp;
                    *reinterpret_cast<bf162*>(Cl + o) = lp;
                }
            }
        }
    }

    if (MODE == 3) {
        // Reduce over g (lane bits 2..4), then lanes 0..3 do the atomics.
        float* st = stats + (size_t)z * 2 * COUT;
#pragma unroll
        for (int nf = 0; nf < 4; nf++) {
#pragma unroll
            for (int p = 0; p < 2; p++) {
#pragma unroll
                for (int off = 4; off <= 16; off <<= 1) {
                    ts[nf][p] += __shfl_xor_sync(0xFFFFFFFFu, ts[nf][p], off);
                    tq[nf][p] += __shfl_xor_sync(0xFFFFFFFFu, tq[nf][p], off);
                }
            }
        }
        if (lane < 4) {
#pragma unroll
            for (int nf = 0; nf < 4; nf++) {
                int col = nTile * 128 + n0 + nf * 8 + tg * 2;
                atomicAdd(&st[col],            ts[nf][0]);
                atomicAdd(&st[col + 1],        ts[nf][1]);
                atomicAdd(&st[COUT + col],     tq[nf][0]);
                atomicAdd(&st[COUT + col + 1], tq[nf][1]);
            }
        }
    }
}

// ---------------------------------------------------------------------------
// fp32 -> bf16 hi/lo split, vectorized (float4 in, uint2 out per array)
// ---------------------------------------------------------------------------
__global__ void __launch_bounds__(256)
split_act4(const float* __restrict__ a0, const float* __restrict__ a1,
           bf16* __restrict__ oh, bf16* __restrict__ ol, int n4)
{
    const int z = blockIdx.y;
    const float* a = z ? a1 : a0;
    const size_t off = (size_t)z * n4;
    int i = blockIdx.x * 256 + threadIdx.x;
    if (i < n4) {
        float4 v = reinterpret_cast<const float4*>(a)[i];
        bf16 h0, l0, h1, l1, h2, l2, h3, l3;
        split_f32(v.x, h0, l0); split_f32(v.y, h1, l1);
        split_f32(v.z, h2, l2); split_f32(v.w, h3, l3);
        bf162 hA; hA.x = h0; hA.y = h1;
        bf162 hB; hB.x = h2; hB.y = h3;
        bf162 lA; lA.x = l0; lA.y = l1;
        bf162 lB; lB.x = l2; lB.y = l3;
        uint2 hp, lp;
        hp.x = *reinterpret_cast<uint32_t*>(&hA);
        hp.y = *reinterpret_cast<uint32_t*>(&hB);
        lp.x = *reinterpret_cast<uint32_t*>(&lA);
        lp.y = *reinterpret_cast<uint32_t*>(&lB);
        reinterpret_cast<uint2*>(oh)[off + i] = hp;
        reinterpret_cast<uint2*>(ol)[off + i] = lp;
    }
}

__global__ void __launch_bounds__(256)
split_w(const float* __restrict__ in, bf16* __restrict__ oh, bf16* __restrict__ ol, int n)
{
    int i = blockIdx.x * 256 + threadIdx.x;
    if (i < n) {
        bf16 h, l;
        split_f32(in[i], h, l);
        oh[i] = h;
        ol[i] = l;
    }
}

// ---------------------------------------------------------------------------
// KPConv aggregation: agg[n, p*CMID + c] = sum_k infl(n,k,p) * h[nb(n,k), c]
// h stored interleaved (hi,lo) -> single 4B load per (nb, ch).
// ---------------------------------------------------------------------------
__global__ void __launch_bounds__(128)
kpconv_agg(const bf162* __restrict__ hil,
           const float* __restrict__ coords0, const float* __restrict__ coords1,
           const int* __restrict__ neighb0, const int* __restrict__ neighb1,
           const float* __restrict__ kpts,
           bf16* __restrict__ aggh, bf16* __restrict__ aggl)
{
    const int z = blockIdx.z;
    const float* coords = z ? coords1 : coords0;
    const int*   neighb = z ? neighb1 : neighb0;
    const size_t brH = (size_t)z * NPTS * CMID;
    const size_t brA = (size_t)z * NPTS * PC;

    const int n = blockIdx.x;
    const int t = threadIdx.x;

    __shared__ int   nb[KNB];
    __shared__ float rel[KNB][3];
    __shared__ float infl[KNB][PKP + 1];

    if (t < KNB) nb[t] = neighb[n * KNB + t];
    __syncthreads();
    if (t < KNB * 3) {
        int k = t / 3, d = t % 3;
        rel[k][d] = coords[(size_t)nb[k] * 3 + d] - coords[(size_t)n * 3 + d];
    }
    __syncthreads();
    for (int idx = t; idx < KNB * PKP; idx += 128) {
        int k = idx / PKP, p = idx % PKP;
        float dx = rel[k][0] - kpts[p * 3 + 0];
        float dy = rel[k][1] - kpts[p * 3 + 1];
        float dz = rel[k][2] - kpts[p * 3 + 2];
        float d  = sqrtf(dx * dx + dy * dy + dz * dz);
        infl[k][p] = fmaxf(0.0f, 1.0f - d * 1.25f);   // EXTENT = 0.8
    }
    __syncthreads();

    float acc[PKP];
#pragma unroll
    for (int p = 0; p < PKP; p++) acc[p] = 0.0f;

#pragma unroll 4
    for (int k = 0; k < KNB; k++) {
        bf162 pr = __ldg(&hil[brH + (size_t)nb[k] * CMID + t]);
        float f = __bfloat162float(pr.x) + __bfloat162float(pr.y);
#pragma unroll
        for (int p = 0; p < PKP; p++)
            acc[p] = fmaf(infl[k][p], f, acc[p]);
    }

#pragma unroll
    for (int p = 0; p < PKP; p++) {
        size_t o = brA + (size_t)n * PC + (size_t)p * CMID + t;
        bf16 h, l;
        split_f32(acc[p], h, l);
        aggh[o] = h;
        aggl[o] = l;
    }
}

// ---------------------------------------------------------------------------
// BatchNorm apply (stats already accumulated by GEMM2 epilogue)
// ---------------------------------------------------------------------------
__global__ void zero_stats(float* s)
{
    s[blockIdx.x * 1024 + threadIdx.x] = 0.0f;   // <<<2, 1024>>>
}

__global__ void __launch_bounds__(256)
bn_apply4(const float* __restrict__ ybase, const float* __restrict__ stats,
          const float* __restrict__ gamma, const float* __restrict__ beta,
          float* __restrict__ outbase)
{
    const int z = blockIdx.y;
    const float* y   = ybase + (size_t)z * NPTS * COUT;
    const float* st  = stats + (size_t)z * 2 * COUT;
    float*       out = outbase + (size_t)z * NPTS * COUT;

    const int i = blockIdx.x * blockDim.x + threadIdx.x;   // float4 index
    const int c = (i * 4) & (COUT - 1);
    float4 v = reinterpret_cast<const float4*>(y)[i];
    float r[4] = {v.x, v.y, v.z, v.w};
#pragma unroll
    for (int j = 0; j < 4; j++) {
        float mu  = st[c + j] * (1.0f / NPTS);
        float var = st[COUT + c + j] * (1.0f / NPTS) - mu * mu;
        float scale = rsqrtf(var + 1e-5f) * gamma[c + j];
        float t = (r[j] - mu) * scale + beta[c + j];
        r[j] = (t >= 0.0f) ? t : 0.1f * t;
    }
    reinterpret_cast<float4*>(out)[i] = make_float4(r[0], r[1], r[2], r[3]);
}

__global__ void copy_coords(const float* __restrict__ a, const float* __restrict__ b,
                            float* __restrict__ out)
{
    int i = blockIdx.x * blockDim.x + threadIdx.x;
    if (i < NPTS * 3) {
        out[i]            = a[i];
        out[NPTS * 3 + i] = b[i];
    }
}

// ---------------------------------------------------------------------------
// Launcher
// ---------------------------------------------------------------------------
#define SMEM_DYN (3 * STAGE_BYTES)

extern "C" void kernel_launch(void* const* d_in, const int* in_sizes, int n_in,
                              void* d_out, int out_size)
{
    (void)in_sizes; (void)n_in; (void)out_size;

    const float* src    = (const float*)d_in[0];
    const float* tgt    = (const float*)d_in[1];
    const float* sc     = (const float*)d_in[2];
    const float* tc     = (const float*)d_in[3];
    const int*   snb    = (const int*)  d_in[4];
    const int*   tnb    = (const int*)  d_in[5];
    const float* W_in   = (const float*)d_in[6];
    const float* b_in   = (const float*)d_in[7];
    const float* kpts   = (const float*)d_in[8];
    const float* kpw    = (const float*)d_in[9];    // [1920, 128] = [K, N]
    const float* W_out  = (const float*)d_in[10];
    const float* b_out  = (const float*)d_in[11];
    const float* gamma  = (const float*)d_in[12];
    const float* beta   = (const float*)d_in[13];
    float* out = (float*)d_out;

    bf16 *xs_h, *xs_l, *ag_h, *ag_l, *md_h, *md_l;
    bf16 *wi_h, *wi_l, *kw_h, *kw_l, *wo_h, *wo_l;
    bf162* h_il;
    float *y, *stats;
    cudaGetSymbolAddress((void**)&xs_h, g_xs_h);  cudaGetSymbolAddress((void**)&xs_l, g_xs_l);
    cudaGetSymbolAddress((void**)&h_il, g_h_il);
    cudaGetSymbolAddress((void**)&ag_h, g_ag_h);  cudaGetSymbolAddress((void**)&ag_l, g_ag_l);
    cudaGetSymbolAddress((void**)&md_h, g_md_h);  cudaGetSymbolAddress((void**)&md_l, g_md_l);
    cudaGetSymbolAddress((void**)&wi_h, g_wi_h);  cudaGetSymbolAddress((void**)&wi_l, g_wi_l);
    cudaGetSymbolAddress((void**)&kw_h, g_kw_h);  cudaGetSymbolAddress((void**)&kw_l, g_kw_l);
    cudaGetSymbolAddress((void**)&wo_h, g_wo_h);  cudaGetSymbolAddress((void**)&wo_l, g_wo_l);
    cudaGetSymbolAddress((void**)&y, g_y);
    cudaGetSymbolAddress((void**)&stats, g_stats);

    cudaFuncSetAttribute(mma_gemm<0>, cudaFuncAttributeMaxDynamicSharedMemorySize, SMEM_DYN);
    cudaFuncSetAttribute(mma_gemm<2>, cudaFuncAttributeMaxDynamicSharedMemorySize, SMEM_DYN);
    cudaFuncSetAttribute(mma_gemm<3>, cudaFuncAttributeMaxDynamicSharedMemorySize, SMEM_DYN);

    // Weight splits (already [K, N])
    split_w<<<(CIN * CMID + 255) / 256, 256>>>(W_in, wi_h, wi_l, CIN * CMID);
    split_w<<<(PC * CMID + 255) / 256, 256>>>(kpw, kw_h, kw_l, PC * CMID);
    split_w<<<(CMID * COUT + 255) / 256, 256>>>(W_out, wo_h, wo_l, CMID * COUT);

    // Split input activations (both branches), vectorized
    split_act4<<<dim3((NPTS * CIN / 4 + 255) / 256, 2), 256>>>(
        src, tgt, xs_h, xs_l, NPTS * CIN / 4);

    // Zero BN stats (consumed by GEMM2 epilogue atomics)
    zero_stats<<<2, 1024>>>(stats);

    // GEMM1: h = x @ W_in + b_in -> interleaved (hi,lo)
    mma_gemm<2><<<dim3(1, NPTS / 128, 2), 256, SMEM_DYN>>>(
        xs_h, xs_l, wi_h, wi_l, b_in, nullptr, nullptr, nullptr, h_il, nullptr, CIN, CMID);

    // KPConv gather + aggregation -> agg split bf16 [16384, 1920]
    kpconv_agg<<<dim3(NPTS, 1, 2), 128>>>(h_il, sc, tc, snb, tnb, kpts, ag_h, ag_l);

    // mid = agg @ kpw -> split bf16
    mma_gemm<0><<<dim3(1, NPTS / 128, 2), 256, SMEM_DYN>>>(
        ag_h, ag_l, kw_h, kw_l, nullptr, nullptr, md_h, md_l, nullptr, nullptr, PC, CMID);

    // y = mid @ W_out + b_out -> fp32 + fused BN stats
    mma_gemm<3><<<dim3(COUT / 128, NPTS / 128, 2), 256, SMEM_DYN>>>(
        md_h, md_l, wo_h, wo_l, b_out, y, nullptr, nullptr, nullptr, stats, CMID, COUT);

    // BN normalize + LeakyReLU
    bn_apply4<<<dim3((NPTS * COUT / 4) / 256, 2), 256>>>(y, stats, gamma, beta, out);

    // coords pass-through
    copy_coords<<<(NPTS * 3 + 255) / 256, 256>>>(sc, tc, out + 2ull * NPTS * COUT);
}

// round 6
// speedup vs baseline: 2.2921x; 1.1107x over previous
#include <cuda_runtime.h>
#include <cuda_bf16.h>
#include <cuda_fp16.h>
#include <math.h>
#include <stdint.h>

#define NPTS 16384
#define KNB  32
#define PKP  15
#define CIN  256
#define CMID 128
#define COUT 512
#define PC   (PKP * CMID)   // 1920

typedef unsigned long long ull;
typedef __nv_bfloat16 bf16;
typedef __nv_bfloat162 bf162;
typedef __half f16;

// ---------------------------------------------------------------------------
// Scratch (device globals -- allocation-free)
// ---------------------------------------------------------------------------
__device__ __align__(128) bf16  g_xs_h[2ull * NPTS * CIN],  g_xs_l[2ull * NPTS * CIN];
__device__ __align__(128) bf162 g_h_il[2ull * NPTS * CMID];                 // (hi,lo) pairs
__device__ __align__(128) f16   g_ag  [2ull * NPTS * PC];                   // fp16 single
__device__ __align__(128) bf16  g_md_h[2ull * NPTS * CMID], g_md_l[2ull * NPTS * CMID];
__device__ __align__(128) float g_y  [2ull * NPTS * COUT];
__device__ __align__(128) bf16  g_wi_h[CIN * CMID],  g_wi_l[CIN * CMID];    // [K,N]
__device__ __align__(128) f16   g_kw_h[PC * CMID],   g_kw_l[PC * CMID];     // [K,N] fp16 split
__device__ __align__(128) bf16  g_wo_h[CMID * COUT], g_wo_l[CMID * COUT];   // [K,N]
__device__ float g_stats[2 * 2 * COUT];

// ---------------------------------------------------------------------------
// PTX helpers (sm_80+ portable, legal on compute_103)
// ---------------------------------------------------------------------------
__device__ __forceinline__ uint32_t s2u(const void* p)
{
    return (uint32_t)__cvta_generic_to_shared(p);
}
__device__ __forceinline__ void cpa16(uint32_t s, const void* g)
{
    asm volatile("cp.async.cg.shared.global [%0], [%1], 16;" :: "r"(s), "l"(g));
}
__device__ __forceinline__ void cp_commit()
{
    asm volatile("cp.async.commit_group;" ::: "memory");
}
template <int N>
__device__ __forceinline__ void cp_wait()
{
    asm volatile("cp.async.wait_group %0;" :: "n"(N) : "memory");
}
__device__ __forceinline__ void ldsm4(uint32_t* r, uint32_t a)
{
    asm volatile("ldmatrix.sync.aligned.m8n8.x4.shared.b16 {%0,%1,%2,%3}, [%4];"
                 : "=r"(r[0]), "=r"(r[1]), "=r"(r[2]), "=r"(r[3]) : "r"(a));
}
__device__ __forceinline__ void ldsm4t(uint32_t* r, uint32_t a)
{
    asm volatile("ldmatrix.sync.aligned.m8n8.x4.trans.shared.b16 {%0,%1,%2,%3}, [%4];"
                 : "=r"(r[0]), "=r"(r[1]), "=r"(r[2]), "=r"(r[3]) : "r"(a));
}
__device__ __forceinline__ void mma_bf(float* c, const uint32_t* a, const uint32_t* b)
{
    asm volatile(
        "mma.sync.aligned.m16n8k16.row.col.f32.bf16.bf16.f32 "
        "{%0,%1,%2,%3}, {%4,%5,%6,%7}, {%8,%9}, {%0,%1,%2,%3};"
        : "+f"(c[0]), "+f"(c[1]), "+f"(c[2]), "+f"(c[3])
        : "r"(a[0]), "r"(a[1]), "r"(a[2]), "r"(a[3]), "r"(b[0]), "r"(b[1]));
}
__device__ __forceinline__ void mma_hf(float* c, const uint32_t* a, const uint32_t* b)
{
    asm volatile(
        "mma.sync.aligned.m16n8k16.row.col.f32.f16.f16.f32 "
        "{%0,%1,%2,%3}, {%4,%5,%6,%7}, {%8,%9}, {%0,%1,%2,%3};"
        : "+f"(c[0]), "+f"(c[1]), "+f"(c[2]), "+f"(c[3])
        : "r"(a[0]), "r"(a[1]), "r"(a[2]), "r"(a[3]), "r"(b[0]), "r"(b[1]));
}
__device__ __forceinline__ void split_f32(float v, bf16& h, bf16& l)
{
    h = __float2bfloat16(v);
    l = __float2bfloat16(v - __bfloat162float(h));
}

// ---------------------------------------------------------------------------
// bf16x3 HMMA GEMM (A,B split bf16), 3-stage cp.async pipeline.
// CTA tile 128x128, BK=64, 8 warps (2m x 4n), warp tile 64x32.
// Stage (64KB): Ah[16K] Al[16K] Bh[16K] Bl[16K]; 3 stages = 192KB.
// MODE 0: C -> bf16 hi/lo split. MODE 2: interleaved (hi,lo) bf162 (+bias).
// MODE 3: fp32 (+bias) AND per-channel BN stats via atomics.
// ---------------------------------------------------------------------------
#define STAGE_BYTES 65536

__device__ __forceinline__ void issue_chunk(
    const bf16* gAh, const bf16* gAl, const bf16* gBh, const bf16* gBl,
    int K, int Ntot, int c, uint32_t sb, int tid)
{
    const int kt = c * 64;
#pragma unroll
    for (int i = 0; i < 4; i++) {
        int idx = tid + i * 256;            // A: 128 rows x 8 16B-chunks
        int r = idx >> 3, ch = idx & 7;
        uint32_t off = (uint32_t)(r * 128 + ((ch ^ (r & 7)) << 4));
        size_t go = (size_t)r * K + kt + ch * 8;
        cpa16(sb + off,         gAh + go);
        cpa16(sb + 16384 + off, gAl + go);
    }
#pragma unroll
    for (int i = 0; i < 4; i++) {
        int idx = tid + i * 256;            // B: 64 rows x 16 16B-chunks
        int r = idx >> 4, ch = idx & 15;
        uint32_t off = (uint32_t)(r * 256 + ((ch ^ (r & 7)) << 4));
        size_t go = (size_t)(kt + r) * Ntot + ch * 8;
        cpa16(sb + 32768 + off, gBh + go);
        cpa16(sb + 49152 + off, gBl + go);
    }
    cp_commit();
}

template <int MODE>
__global__ void __launch_bounds__(256)
mma_gemm(const bf16* __restrict__ Ah, const bf16* __restrict__ Al,
         const bf16* __restrict__ Bh, const bf16* __restrict__ Bl,
         const float* __restrict__ bias,
         float* __restrict__ Cf, bf16* __restrict__ Ch, bf16* __restrict__ Cl,
         bf162* __restrict__ Cil, float* __restrict__ stats,
         int K, int Ntot)
{
    extern __shared__ char smem[];
    const uint32_t sb0 = s2u(smem);

    const int tid  = threadIdx.x;
    const int wid  = tid >> 5;
    const int lane = tid & 31;
    const int z     = blockIdx.z;
    const int mTile = blockIdx.y;
    const int nTile = blockIdx.x;

    const int m0 = (wid & 1) * 64;
    const int n0 = (wid >> 1) * 32;

    const size_t brA = (size_t)z * NPTS * K;
    const size_t brC = (size_t)z * NPTS * Ntot;
    const bf16* gAh = Ah + brA + (size_t)mTile * 128 * K;
    const bf16* gAl = Al + brA + (size_t)mTile * 128 * K;
    const bf16* gBh = Bh + (size_t)nTile * 128;
    const bf16* gBl = Bl + (size_t)nTile * 128;

    float acc[4][4][4];
#pragma unroll
    for (int i = 0; i < 4; i++)
#pragma unroll
        for (int j = 0; j < 4; j++)
#pragma unroll
            for (int t = 0; t < 4; t++) acc[i][j][t] = 0.0f;

    const int nch = K >> 6;
    issue_chunk(gAh, gAl, gBh, gBl, K, Ntot, 0, sb0, tid);
    if (nch > 1)
        issue_chunk(gAh, gAl, gBh, gBl, K, Ntot, 1, sb0 + STAGE_BYTES, tid);
    else
        cp_commit();

    int bufn = 2 % 3;
    for (int c = 0; c < nch; c++) {
        if (c + 2 < nch)
            issue_chunk(gAh, gAl, gBh, gBl, K, Ntot, c + 2,
                        sb0 + bufn * STAGE_BYTES, tid);
        else
            cp_commit();
        bufn = (bufn + 1) % 3;
        cp_wait<2>();
        __syncthreads();

        const uint32_t sb = sb0 + (c % 3) * STAGE_BYTES;
        const uint32_t sA = sb, sB = sb + 32768;

#pragma unroll
        for (int ks = 0; ks < 4; ks++) {
            uint32_t bh[4][2], bl[4][2];
#pragma unroll
            for (int pr = 0; pr < 2; pr++) {
                int k   = ks * 16 + (lane & 15);
                int chn = ((n0 + pr * 16) >> 3) + (lane >> 4);
                uint32_t ba = sB + (uint32_t)(k * 256 + ((chn ^ (k & 7)) << 4));
                uint32_t t[4];
                ldsm4t(t, ba);
                bh[pr * 2][0] = t[0]; bh[pr * 2][1] = t[1];
                bh[pr * 2 + 1][0] = t[2]; bh[pr * 2 + 1][1] = t[3];
                ldsm4t(t, ba + 16384);
                bl[pr * 2][0] = t[0]; bl[pr * 2][1] = t[1];
                bl[pr * 2 + 1][0] = t[2]; bl[pr * 2 + 1][1] = t[3];
            }
#pragma unroll
            for (int mf = 0; mf < 4; mf++) {
                int r   = m0 + mf * 16 + (lane & 15);
                int chk = ks * 2 + (lane >> 4);
                uint32_t aa = sA + (uint32_t)(r * 128 + ((chk ^ (r & 7)) << 4));
                uint32_t ah[4], al[4];
                ldsm4(ah, aa);
                ldsm4(al, aa + 16384);
#pragma unroll
                for (int nf = 0; nf < 4; nf++) {
                    mma_bf(acc[mf][nf], ah, bh[nf]);
                    mma_bf(acc[mf][nf], ah, bl[nf]);
                    mma_bf(acc[mf][nf], al, bh[nf]);
                }
            }
        }
        __syncthreads();
    }

    const int g  = lane >> 2;
    const int tg = lane & 3;

    float ts[4][2], tq[4][2];
    if (MODE == 3) {
#pragma unroll
        for (int nf = 0; nf < 4; nf++)
            ts[nf][0] = ts[nf][1] = tq[nf][0] = tq[nf][1] = 0.0f;
    }

#pragma unroll
    for (int mf = 0; mf < 4; mf++) {
#pragma unroll
        for (int nf = 0; nf < 4; nf++) {
            int col = nTile * 128 + n0 + nf * 8 + tg * 2;
            float b0 = bias ? bias[col] : 0.0f;
            float b1 = bias ? bias[col + 1] : 0.0f;
#pragma unroll
            for (int hrow = 0; hrow < 2; hrow++) {
                int row = mTile * 128 + m0 + mf * 16 + g + hrow * 8;
                float v0 = acc[mf][nf][hrow * 2 + 0] + b0;
                float v1 = acc[mf][nf][hrow * 2 + 1] + b1;
                size_t o = brC + (size_t)row * Ntot + col;
                if (MODE == 3) {
                    *reinterpret_cast<float2*>(Cf + o) = make_float2(v0, v1);
                    ts[nf][0] += v0;           tq[nf][0] = fmaf(v0, v0, tq[nf][0]);
                    ts[nf][1] += v1;           tq[nf][1] = fmaf(v1, v1, tq[nf][1]);
                } else if (MODE == 2) {
                    bf16 h0, l0, h1, l1;
                    split_f32(v0, h0, l0);
                    split_f32(v1, h1, l1);
                    bf162 p0; p0.x = h0; p0.y = l0;
                    bf162 p1; p1.x = h1; p1.y = l1;
                    uint2 pk;
                    pk.x = *reinterpret_cast<uint32_t*>(&p0);
                    pk.y = *reinterpret_cast<uint32_t*>(&p1);
                    *reinterpret_cast<uint2*>(Cil + o) = pk;
                } else {
                    bf16 h0, l0, h1, l1;
                    split_f32(v0, h0, l0);
                    split_f32(v1, h1, l1);
                    bf162 hp; hp.x = h0; hp.y = h1;
                    bf162 lp; lp.x = l0; lp.y = l1;
                    *reinterpret_cast<bf162*>(Ch + o) = hp;
                    *reinterpret_cast<bf162*>(Cl + o) = lp;
                }
            }
        }
    }

    if (MODE == 3) {
        float* st = stats + (size_t)z * 2 * COUT;
#pragma unroll
        for (int nf = 0; nf < 4; nf++) {
#pragma unroll
            for (int p = 0; p < 2; p++) {
#pragma unroll
                for (int off = 4; off <= 16; off <<= 1) {
                    ts[nf][p] += __shfl_xor_sync(0xFFFFFFFFu, ts[nf][p], off);
                    tq[nf][p] += __shfl_xor_sync(0xFFFFFFFFu, tq[nf][p], off);
                }
            }
        }
        if (lane < 4) {
#pragma unroll
            for (int nf = 0; nf < 4; nf++) {
                int col = nTile * 128 + n0 + nf * 8 + tg * 2;
                atomicAdd(&st[col],            ts[nf][0]);
                atomicAdd(&st[col + 1],        ts[nf][1]);
                atomicAdd(&st[COUT + col],     tq[nf][0]);
                atomicAdd(&st[COUT + col + 1], tq[nf][1]);
            }
        }
    }
}

// ---------------------------------------------------------------------------
// fp16-A HMMA GEMM for the mid GEMM: A fp16 single, B fp16 hi/lo split.
// C = A @ (Bh + Bl); 2 MMAs per fragment. Ntot = 128, nTile = 0 always.
// Stage (48KB): A[16K] Bh[16K] Bl[16K]; 3 stages = 144KB.
// Output: split bf16 (for GEMM3's bf16x3 A input).
// ---------------------------------------------------------------------------
#define STAGE_F16 49152

__device__ __forceinline__ void issue_chunk_f16(
    const f16* gA, const f16* gBh, const f16* gBl,
    int K, int c, uint32_t sb, int tid)
{
    const int kt = c * 64;
#pragma unroll
    for (int i = 0; i < 4; i++) {
        int idx = tid + i * 256;            // A: 128 rows x 8 16B-chunks
        int r = idx >> 3, ch = idx & 7;
        uint32_t off = (uint32_t)(r * 128 + ((ch ^ (r & 7)) << 4));
        cpa16(sb + off, gA + (size_t)r * K + kt + ch * 8);
    }
#pragma unroll
    for (int i = 0; i < 4; i++) {
        int idx = tid + i * 256;            // B: 64 rows x 16 16B-chunks
        int r = idx >> 4, ch = idx & 15;
        uint32_t off = (uint32_t)(r * 256 + ((ch ^ (r & 7)) << 4));
        size_t go = (size_t)(kt + r) * CMID + ch * 8;
        cpa16(sb + 16384 + off, gBh + go);
        cpa16(sb + 32768 + off, gBl + go);
    }
    cp_commit();
}

__global__ void __launch_bounds__(256)
mma_gemm_f16A(const f16* __restrict__ A, const f16* __restrict__ Bh,
              const f16* __restrict__ Bl,
              bf16* __restrict__ Ch, bf16* __restrict__ Cl, int K)
{
    extern __shared__ char smem[];
    const uint32_t sb0 = s2u(smem);

    const int tid  = threadIdx.x;
    const int wid  = tid >> 5;
    const int lane = tid & 31;
    const int z     = blockIdx.z;
    const int mTile = blockIdx.y;

    const int m0 = (wid & 1) * 64;
    const int n0 = (wid >> 1) * 32;

    const size_t brA = (size_t)z * NPTS * K;
    const size_t brC = (size_t)z * NPTS * CMID;
    const f16* gA = A + brA + (size_t)mTile * 128 * K;

    float acc[4][4][4];
#pragma unroll
    for (int i = 0; i < 4; i++)
#pragma unroll
        for (int j = 0; j < 4; j++)
#pragma unroll
            for (int t = 0; t < 4; t++) acc[i][j][t] = 0.0f;

    const int nch = K >> 6;
    issue_chunk_f16(gA, Bh, Bl, K, 0, sb0, tid);
    issue_chunk_f16(gA, Bh, Bl, K, 1, sb0 + STAGE_F16, tid);

    int bufn = 2;
    for (int c = 0; c < nch; c++) {
        if (c + 2 < nch)
            issue_chunk_f16(gA, Bh, Bl, K, c + 2, sb0 + bufn * STAGE_F16, tid);
        else
            cp_commit();
        bufn = bufn == 2 ? 0 : bufn + 1;
        cp_wait<2>();
        __syncthreads();

        const uint32_t sb = sb0 + (c % 3) * STAGE_F16;
        const uint32_t sA = sb, sB = sb + 16384;

#pragma unroll
        for (int ks = 0; ks < 4; ks++) {
            uint32_t bh[4][2], bl[4][2];
#pragma unroll
            for (int pr = 0; pr < 2; pr++) {
                int k   = ks * 16 + (lane & 15);
                int chn = ((n0 + pr * 16) >> 3) + (lane >> 4);
                uint32_t ba = sB + (uint32_t)(k * 256 + ((chn ^ (k & 7)) << 4));
                uint32_t t[4];
                ldsm4t(t, ba);
                bh[pr * 2][0] = t[0]; bh[pr * 2][1] = t[1];
                bh[pr * 2 + 1][0] = t[2]; bh[pr * 2 + 1][1] = t[3];
                ldsm4t(t, ba + 16384);
                bl[pr * 2][0] = t[0]; bl[pr * 2][1] = t[1];
                bl[pr * 2 + 1][0] = t[2]; bl[pr * 2 + 1][1] = t[3];
            }
#pragma unroll
            for (int mf = 0; mf < 4; mf++) {
                int r   = m0 + mf * 16 + (lane & 15);
                int chk = ks * 2 + (lane >> 4);
                uint32_t aa = sA + (uint32_t)(r * 128 + ((chk ^ (r & 7)) << 4));
                uint32_t av[4];
                ldsm4(av, aa);
#pragma unroll
                for (int nf = 0; nf < 4; nf++) {
                    mma_hf(acc[mf][nf], av, bh[nf]);
                    mma_hf(acc[mf][nf], av, bl[nf]);
                }
            }
        }
        __syncthreads();
    }

    const int g  = lane >> 2;
    const int tg = lane & 3;
#pragma unroll
    for (int mf = 0; mf < 4; mf++) {
#pragma unroll
        for (int nf = 0; nf < 4; nf++) {
            int col = n0 + nf * 8 + tg * 2;
#pragma unroll
            for (int hrow = 0; hrow < 2; hrow++) {
                int row = mTile * 128 + m0 + mf * 16 + g + hrow * 8;
                float v0 = acc[mf][nf][hrow * 2 + 0];
                float v1 = acc[mf][nf][hrow * 2 + 1];
                size_t o = brC + (size_t)row * CMID + col;
                bf16 h0, l0, h1, l1;
                split_f32(v0, h0, l0);
                split_f32(v1, h1, l1);
                bf162 hp; hp.x = h0; hp.y = h1;
                bf162 lp; lp.x = l0; lp.y = l1;
                *reinterpret_cast<bf162*>(Ch + o) = hp;
                *reinterpret_cast<bf162*>(Cl + o) = lp;
            }
        }
    }
}

// ---------------------------------------------------------------------------
// Conversions
// ---------------------------------------------------------------------------
__global__ void __launch_bounds__(256)
split_act4(const float* __restrict__ a0, const float* __restrict__ a1,
           bf16* __restrict__ oh, bf16* __restrict__ ol, int n4)
{
    const int z = blockIdx.y;
    const float* a = z ? a1 : a0;
    const size_t off = (size_t)z * n4;
    int i = blockIdx.x * 256 + threadIdx.x;
    if (i < n4) {
        float4 v = reinterpret_cast<const float4*>(a)[i];
        bf16 h0, l0, h1, l1, h2, l2, h3, l3;
        split_f32(v.x, h0, l0); split_f32(v.y, h1, l1);
        split_f32(v.z, h2, l2); split_f32(v.w, h3, l3);
        bf162 hA; hA.x = h0; hA.y = h1;
        bf162 hB; hB.x = h2; hB.y = h3;
        bf162 lA; lA.x = l0; lA.y = l1;
        bf162 lB; lB.x = l2; lB.y = l3;
        uint2 hp, lp;
        hp.x = *reinterpret_cast<uint32_t*>(&hA);
        hp.y = *reinterpret_cast<uint32_t*>(&hB);
        lp.x = *reinterpret_cast<uint32_t*>(&lA);
        lp.y = *reinterpret_cast<uint32_t*>(&lB);
        reinterpret_cast<uint2*>(oh)[off + i] = hp;
        reinterpret_cast<uint2*>(ol)[off + i] = lp;
    }
}

__global__ void __launch_bounds__(256)
split_w(const float* __restrict__ in, bf16* __restrict__ oh, bf16* __restrict__ ol, int n)
{
    int i = blockIdx.x * 256 + threadIdx.x;
    if (i < n) {
        bf16 h, l;
        split_f32(in[i], h, l);
        oh[i] = h;
        ol[i] = l;
    }
}

__global__ void __launch_bounds__(256)
split_w_f16(const float* __restrict__ in, f16* __restrict__ oh, f16* __restrict__ ol, int n)
{
    int i = blockIdx.x * 256 + threadIdx.x;
    if (i < n) {
        float v = in[i];
        f16 h = __float2half(v);
        oh[i] = h;
        ol[i] = __float2half(v - __half2float(h));
    }
}

// ---------------------------------------------------------------------------
// KPConv aggregation -> fp16 agg
// ---------------------------------------------------------------------------
__global__ void __launch_bounds__(128)
kpconv_agg(const bf162* __restrict__ hil,
           const float* __restrict__ coords0, const float* __restrict__ coords1,
           const int* __restrict__ neighb0, const int* __restrict__ neighb1,
           const float* __restrict__ kpts, f16* __restrict__ agg)
{
    const int z = blockIdx.z;
    const float* coords = z ? coords1 : coords0;
    const int*   neighb = z ? neighb1 : neighb0;
    const size_t brH = (size_t)z * NPTS * CMID;
    const size_t brA = (size_t)z * NPTS * PC;

    const int n = blockIdx.x;
    const int t = threadIdx.x;

    __shared__ int   nb[KNB];
    __shared__ float rel[KNB][3];
    __shared__ float infl[KNB][PKP + 1];

    if (t < KNB) nb[t] = neighb[n * KNB + t];
    __syncthreads();
    if (t < KNB * 3) {
        int k = t / 3, d = t % 3;
        rel[k][d] = coords[(size_t)nb[k] * 3 + d] - coords[(size_t)n * 3 + d];
    }
    __syncthreads();
    for (int idx = t; idx < KNB * PKP; idx += 128) {
        int k = idx / PKP, p = idx % PKP;
        float dx = rel[k][0] - kpts[p * 3 + 0];
        float dy = rel[k][1] - kpts[p * 3 + 1];
        float dz = rel[k][2] - kpts[p * 3 + 2];
        float d  = sqrtf(dx * dx + dy * dy + dz * dz);
        infl[k][p] = fmaxf(0.0f, 1.0f - d * 1.25f);   // EXTENT = 0.8
    }
    __syncthreads();

    float acc[PKP];
#pragma unroll
    for (int p = 0; p < PKP; p++) acc[p] = 0.0f;

#pragma unroll 4
    for (int k = 0; k < KNB; k++) {
        bf162 pr = __ldg(&hil[brH + (size_t)nb[k] * CMID + t]);
        float f = __bfloat162float(pr.x) + __bfloat162float(pr.y);
#pragma unroll
        for (int p = 0; p < PKP; p++)
            acc[p] = fmaf(infl[k][p], f, acc[p]);
    }

    f16* o = agg + brA + (size_t)n * PC + t;
#pragma unroll
    for (int p = 0; p < PKP; p++)
        o[(size_t)p * CMID] = __float2half(acc[p]);
}

// ---------------------------------------------------------------------------
// BatchNorm apply (stats accumulated by GEMM3 epilogue)
// ---------------------------------------------------------------------------
__global__ void zero_stats(float* s)
{
    s[blockIdx.x * 1024 + threadIdx.x] = 0.0f;   // <<<2, 1024>>>
}

__global__ void __launch_bounds__(256)
bn_apply4(const float* __restrict__ ybase, const float* __restrict__ stats,
          const float* __restrict__ gamma, const float* __restrict__ beta,
          float* __restrict__ outbase)
{
    const int z = blockIdx.y;
    const float* y   = ybase + (size_t)z * NPTS * COUT;
    const float* st  = stats + (size_t)z * 2 * COUT;
    float*       out = outbase + (size_t)z * NPTS * COUT;

    const int i = blockIdx.x * blockDim.x + threadIdx.x;
    const int c = (i * 4) & (COUT - 1);
    float4 v = reinterpret_cast<const float4*>(y)[i];
    float r[4] = {v.x, v.y, v.z, v.w};
#pragma unroll
    for (int j = 0; j < 4; j++) {
        float mu  = st[c + j] * (1.0f / NPTS);
        float var = st[COUT + c + j] * (1.0f / NPTS) - mu * mu;
        float scale = rsqrtf(var + 1e-5f) * gamma[c + j];
        float t = (r[j] - mu) * scale + beta[c + j];
        r[j] = (t >= 0.0f) ? t : 0.1f * t;
    }
    reinterpret_cast<float4*>(out)[i] = make_float4(r[0], r[1], r[2], r[3]);
}

__global__ void copy_coords(const float* __restrict__ a, const float* __restrict__ b,
                            float* __restrict__ out)
{
    int i = blockIdx.x * blockDim.x + threadIdx.x;
    if (i < NPTS * 3) {
        out[i]            = a[i];
        out[NPTS * 3 + i] = b[i];
    }
}

// ---------------------------------------------------------------------------
// Launcher
// ---------------------------------------------------------------------------
#define SMEM_DYN  (3 * STAGE_BYTES)
#define SMEM_DYN2 (3 * STAGE_F16)

extern "C" void kernel_launch(void* const* d_in, const int* in_sizes, int n_in,
                              void* d_out, int out_size)
{
    (void)in_sizes; (void)n_in; (void)out_size;

    const float* src    = (const float*)d_in[0];
    const float* tgt    = (const float*)d_in[1];
    const float* sc     = (const float*)d_in[2];
    const float* tc     = (const float*)d_in[3];
    const int*   snb    = (const int*)  d_in[4];
    const int*   tnb    = (const int*)  d_in[5];
    const float* W_in   = (const float*)d_in[6];
    const float* b_in   = (const float*)d_in[7];
    const float* kpts   = (const float*)d_in[8];
    const float* kpw    = (const float*)d_in[9];
    const float* W_out  = (const float*)d_in[10];
    const float* b_out  = (const float*)d_in[11];
    const float* gamma  = (const float*)d_in[12];
    const float* beta   = (const float*)d_in[13];
    float* out = (float*)d_out;

    bf16 *xs_h, *xs_l, *md_h, *md_l, *wi_h, *wi_l, *wo_h, *wo_l;
    f16 *ag, *kw_h, *kw_l;
    bf162* h_il;
    float *y, *stats;
    cudaGetSymbolAddress((void**)&xs_h, g_xs_h);  cudaGetSymbolAddress((void**)&xs_l, g_xs_l);
    cudaGetSymbolAddress((void**)&h_il, g_h_il);
    cudaGetSymbolAddress((void**)&ag,   g_ag);
    cudaGetSymbolAddress((void**)&md_h, g_md_h);  cudaGetSymbolAddress((void**)&md_l, g_md_l);
    cudaGetSymbolAddress((void**)&wi_h, g_wi_h);  cudaGetSymbolAddress((void**)&wi_l, g_wi_l);
    cudaGetSymbolAddress((void**)&kw_h, g_kw_h);  cudaGetSymbolAddress((void**)&kw_l, g_kw_l);
    cudaGetSymbolAddress((void**)&wo_h, g_wo_h);  cudaGetSymbolAddress((void**)&wo_l, g_wo_l);
    cudaGetSymbolAddress((void**)&y, g_y);
    cudaGetSymbolAddress((void**)&stats, g_stats);

    cudaFuncSetAttribute(mma_gemm<2>, cudaFuncAttributeMaxDynamicSharedMemorySize, SMEM_DYN);
    cudaFuncSetAttribute(mma_gemm<3>, cudaFuncAttributeMaxDynamicSharedMemorySize, SMEM_DYN);
    cudaFuncSetAttribute(mma_gemm_f16A, cudaFuncAttributeMaxDynamicSharedMemorySize, SMEM_DYN2);

    // Weight preps
    split_w<<<(CIN * CMID + 255) / 256, 256>>>(W_in, wi_h, wi_l, CIN * CMID);
    split_w_f16<<<(PC * CMID + 255) / 256, 256>>>(kpw, kw_h, kw_l, PC * CMID);
    split_w<<<(CMID * COUT + 255) / 256, 256>>>(W_out, wo_h, wo_l, CMID * COUT);

    // Split input activations (both branches)
    split_act4<<<dim3((NPTS * CIN / 4 + 255) / 256, 2), 256>>>(
        src, tgt, xs_h, xs_l, NPTS * CIN / 4);

    // Zero BN stats (consumed by GEMM3 epilogue atomics)
    zero_stats<<<2, 1024>>>(stats);

    // GEMM1: h = x @ W_in + b_in -> interleaved (hi,lo)
    mma_gemm<2><<<dim3(1, NPTS / 128, 2), 256, SMEM_DYN>>>(
        xs_h, xs_l, wi_h, wi_l, b_in, nullptr, nullptr, nullptr, h_il, nullptr, CIN, CMID);

    // KPConv gather + aggregation -> agg fp16 [16384, 1920]
    kpconv_agg<<<dim3(NPTS, 1, 2), 128>>>(h_il, sc, tc, snb, tnb, kpts, ag);

    // mid = agg @ kpw (A fp16, B fp16 split) -> split bf16
    mma_gemm_f16A<<<dim3(1, NPTS / 128, 2), 256, SMEM_DYN2>>>(
        ag, kw_h, kw_l, md_h, md_l, PC);

    // y = mid @ W_out + b_out -> fp32 + fused BN stats
    mma_gemm<3><<<dim3(COUT / 128, NPTS / 128, 2), 256, SMEM_DYN>>>(
        md_h, md_l, wo_h, wo_l, b_out, y, nullptr, nullptr, nullptr, stats, CMID, COUT);

    // BN normalize + LeakyReLU
    bn_apply4<<<dim3((NPTS * COUT / 4) / 256, 2), 256>>>(y, stats, gamma, beta, out);

    // coords pass-through
    copy_coords<<<(NPTS * 3 + 255) / 256, 256>>>(sc, tc, out + 2ull * NPTS * COUT);
}

// round 8
// speedup vs baseline: 2.5312x; 1.1044x over previous
#include <cuda_runtime.h>
#include <cuda_bf16.h>
#include <cuda_fp16.h>
#include <math.h>
#include <stdint.h>

#define NPTS 16384
#define KNB  32
#define PKP  15
#define CIN  256
#define CMID 128
#define COUT 512
#define PC   (PKP * CMID)   // 1920

typedef unsigned long long ull;
typedef __nv_bfloat16 bf16;
typedef __nv_bfloat162 bf162;
typedef __half f16;

// ---------------------------------------------------------------------------
// Scratch (device globals -- allocation-free)
// ---------------------------------------------------------------------------
__device__ __align__(128) f16   g_xs  [2ull * NPTS * CIN];                  // fp16 single
__device__ __align__(128) f16   g_h   [2ull * NPTS * CMID];                 // fp16 single
__device__ __align__(128) f16   g_ag  [2ull * NPTS * PC];                   // fp16 single
__device__ __align__(128) bf16  g_md_h[2ull * NPTS * CMID], g_md_l[2ull * NPTS * CMID];
__device__ __align__(128) float g_y  [2ull * NPTS * COUT];
__device__ __align__(128) f16   g_wi_h[CIN * CMID],  g_wi_l[CIN * CMID];    // fp16 split
__device__ __align__(128) f16   g_kw_h[PC * CMID],   g_kw_l[PC * CMID];     // fp16 split
__device__ __align__(128) bf16  g_wo_h[CMID * COUT], g_wo_l[CMID * COUT];   // bf16 split
__device__ float g_stats[2 * 2 * COUT];

// ---------------------------------------------------------------------------
// PTX helpers (sm_80+ portable, legal on compute_103; f32x2 is Blackwell)
// ---------------------------------------------------------------------------
__device__ __forceinline__ uint32_t s2u(const void* p)
{
    return (uint32_t)__cvta_generic_to_shared(p);
}
__device__ __forceinline__ void cpa16(uint32_t s, const void* g)
{
    asm volatile("cp.async.cg.shared.global [%0], [%1], 16;" :: "r"(s), "l"(g));
}
__device__ __forceinline__ void cp_commit()
{
    asm volatile("cp.async.commit_group;" ::: "memory");
}
template <int N>
__device__ __forceinline__ void cp_wait()
{
    asm volatile("cp.async.wait_group %0;" :: "n"(N) : "memory");
}
__device__ __forceinline__ void ldsm4(uint32_t* r, uint32_t a)
{
    asm volatile("ldmatrix.sync.aligned.m8n8.x4.shared.b16 {%0,%1,%2,%3}, [%4];"
                 : "=r"(r[0]), "=r"(r[1]), "=r"(r[2]), "=r"(r[3]) : "r"(a));
}
__device__ __forceinline__ void ldsm4t(uint32_t* r, uint32_t a)
{
    asm volatile("ldmatrix.sync.aligned.m8n8.x4.trans.shared.b16 {%0,%1,%2,%3}, [%4];"
                 : "=r"(r[0]), "=r"(r[1]), "=r"(r[2]), "=r"(r[3]) : "r"(a));
}
__device__ __forceinline__ void mma_bf(float* c, const uint32_t* a, const uint32_t* b)
{
    asm volatile(
        "mma.sync.aligned.m16n8k16.row.col.f32.bf16.bf16.f32 "
        "{%0,%1,%2,%3}, {%4,%5,%6,%7}, {%8,%9}, {%0,%1,%2,%3};"
        : "+f"(c[0]), "+f"(c[1]), "+f"(c[2]), "+f"(c[3])
        : "r"(a[0]), "r"(a[1]), "r"(a[2]), "r"(a[3]), "r"(b[0]), "r"(b[1]));
}
__device__ __forceinline__ void mma_hf(float* c, const uint32_t* a, const uint32_t* b)
{
    asm volatile(
        "mma.sync.aligned.m16n8k16.row.col.f32.f16.f16.f32 "
        "{%0,%1,%2,%3}, {%4,%5,%6,%7}, {%8,%9}, {%0,%1,%2,%3};"
        : "+f"(c[0]), "+f"(c[1]), "+f"(c[2]), "+f"(c[3])
        : "r"(a[0]), "r"(a[1]), "r"(a[2]), "r"(a[3]), "r"(b[0]), "r"(b[1]));
}
__device__ __forceinline__ void fma2(ull& d, ull a, ull b)
{
    asm("fma.rn.f32x2 %0, %1, %2, %0;" : "+l"(d) : "l"(a), "l"(b));
}
__device__ __forceinline__ ull pack2(float x, float y)
{
    ull r;
    asm("mov.b64 %0, {%1, %2};" : "=l"(r) : "f"(x), "f"(y));
    return r;
}
__device__ __forceinline__ void unpack2(ull v, float& x, float& y)
{
    asm("mov.b64 {%0, %1}, %2;" : "=f"(x), "=f"(y) : "l"(v));
}
__device__ __forceinline__ void split_f32(float v, bf16& h, bf16& l)
{
    h = __float2bfloat16(v);
    l = __float2bfloat16(v - __bfloat162float(h));
}

// ---------------------------------------------------------------------------
// bf16x3 HMMA GEMM (A,B split bf16) -- GEMM3 with fused BN stats.
// CTA tile 128x128, BK=64, 8 warps, warp tile 64x32. 3-stage cp.async.
// ---------------------------------------------------------------------------
#define STAGE_BYTES 65536

__device__ __forceinline__ void issue_chunk(
    const bf16* gAh, const bf16* gAl, const bf16* gBh, const bf16* gBl,
    int K, int Ntot, int c, uint32_t sb, int tid)
{
    const int kt = c * 64;
#pragma unroll
    for (int i = 0; i < 4; i++) {
        int idx = tid + i * 256;
        int r = idx >> 3, ch = idx & 7;
        uint32_t off = (uint32_t)(r * 128 + ((ch ^ (r & 7)) << 4));
        size_t go = (size_t)r * K + kt + ch * 8;
        cpa16(sb + off,         gAh + go);
        cpa16(sb + 16384 + off, gAl + go);
    }
#pragma unroll
    for (int i = 0; i < 4; i++) {
        int idx = tid + i * 256;
        int r = idx >> 4, ch = idx & 15;
        uint32_t off = (uint32_t)(r * 256 + ((ch ^ (r & 7)) << 4));
        size_t go = (size_t)(kt + r) * Ntot + ch * 8;
        cpa16(sb + 32768 + off, gBh + go);
        cpa16(sb + 49152 + off, gBl + go);
    }
    cp_commit();
}

__global__ void __launch_bounds__(256)
mma_gemm_bn(const bf16* __restrict__ Ah, const bf16* __restrict__ Al,
            const bf16* __restrict__ Bh, const bf16* __restrict__ Bl,
            const float* __restrict__ bias,
            float* __restrict__ Cf, float* __restrict__ stats,
            int K, int Ntot)
{
    extern __shared__ char smem[];
    const uint32_t sb0 = s2u(smem);

    const int tid  = threadIdx.x;
    const int wid  = tid >> 5;
    const int lane = tid & 31;
    const int z     = blockIdx.z;
    const int mTile = blockIdx.y;
    const int nTile = blockIdx.x;

    const int m0 = (wid & 1) * 64;
    const int n0 = (wid >> 1) * 32;

    const size_t brA = (size_t)z * NPTS * K;
    const size_t brC = (size_t)z * NPTS * Ntot;
    const bf16* gAh = Ah + brA + (size_t)mTile * 128 * K;
    const bf16* gAl = Al + brA + (size_t)mTile * 128 * K;
    const bf16* gBh = Bh + (size_t)nTile * 128;
    const bf16* gBl = Bl + (size_t)nTile * 128;

    float acc[4][4][4];
#pragma unroll
    for (int i = 0; i < 4; i++)
#pragma unroll
        for (int j = 0; j < 4; j++)
#pragma unroll
            for (int t = 0; t < 4; t++) acc[i][j][t] = 0.0f;

    const int nch = K >> 6;
    issue_chunk(gAh, gAl, gBh, gBl, K, Ntot, 0, sb0, tid);
    if (nch > 1)
        issue_chunk(gAh, gAl, gBh, gBl, K, Ntot, 1, sb0 + STAGE_BYTES, tid);
    else
        cp_commit();

    int bufn = 2 % 3;
    for (int c = 0; c < nch; c++) {
        if (c + 2 < nch)
            issue_chunk(gAh, gAl, gBh, gBl, K, Ntot, c + 2,
                        sb0 + bufn * STAGE_BYTES, tid);
        else
            cp_commit();
        bufn = (bufn + 1) % 3;
        cp_wait<2>();
        __syncthreads();

        const uint32_t sb = sb0 + (c % 3) * STAGE_BYTES;
        const uint32_t sA = sb, sB = sb + 32768;

#pragma unroll
        for (int ks = 0; ks < 4; ks++) {
            uint32_t bh[4][2], bl[4][2];
#pragma unroll
            for (int pr = 0; pr < 2; pr++) {
                int k   = ks * 16 + (lane & 15);
                int chn = ((n0 + pr * 16) >> 3) + (lane >> 4);
                uint32_t ba = sB + (uint32_t)(k * 256 + ((chn ^ (k & 7)) << 4));
                uint32_t t[4];
                ldsm4t(t, ba);
                bh[pr * 2][0] = t[0]; bh[pr * 2][1] = t[1];
                bh[pr * 2 + 1][0] = t[2]; bh[pr * 2 + 1][1] = t[3];
                ldsm4t(t, ba + 16384);
                bl[pr * 2][0] = t[0]; bl[pr * 2][1] = t[1];
                bl[pr * 2 + 1][0] = t[2]; bl[pr * 2 + 1][1] = t[3];
            }
#pragma unroll
            for (int mf = 0; mf < 4; mf++) {
                int r   = m0 + mf * 16 + (lane & 15);
                int chk = ks * 2 + (lane >> 4);
                uint32_t aa = sA + (uint32_t)(r * 128 + ((chk ^ (r & 7)) << 4));
                uint32_t ah[4], al[4];
                ldsm4(ah, aa);
                ldsm4(al, aa + 16384);
#pragma unroll
                for (int nf = 0; nf < 4; nf++) {
                    mma_bf(acc[mf][nf], ah, bh[nf]);
                    mma_bf(acc[mf][nf], ah, bl[nf]);
                    mma_bf(acc[mf][nf], al, bh[nf]);
                }
            }
        }
        __syncthreads();
    }

    const int g  = lane >> 2;
    const int tg = lane & 3;

    float ts[4][2], tq[4][2];
#pragma unroll
    for (int nf = 0; nf < 4; nf++)
        ts[nf][0] = ts[nf][1] = tq[nf][0] = tq[nf][1] = 0.0f;

#pragma unroll
    for (int mf = 0; mf < 4; mf++) {
#pragma unroll
        for (int nf = 0; nf < 4; nf++) {
            int col = nTile * 128 + n0 + nf * 8 + tg * 2;
            float b0 = bias[col];
            float b1 = bias[col + 1];
#pragma unroll
            for (int hrow = 0; hrow < 2; hrow++) {
                int row = mTile * 128 + m0 + mf * 16 + g + hrow * 8;
                float v0 = acc[mf][nf][hrow * 2 + 0] + b0;
                float v1 = acc[mf][nf][hrow * 2 + 1] + b1;
                *reinterpret_cast<float2*>(Cf + brC + (size_t)row * Ntot + col)
                    = make_float2(v0, v1);
                ts[nf][0] += v0;  tq[nf][0] = fmaf(v0, v0, tq[nf][0]);
                ts[nf][1] += v1;  tq[nf][1] = fmaf(v1, v1, tq[nf][1]);
            }
        }
    }

    float* st = stats + (size_t)z * 2 * COUT;
#pragma unroll
    for (int nf = 0; nf < 4; nf++) {
#pragma unroll
        for (int p = 0; p < 2; p++) {
#pragma unroll
            for (int off = 4; off <= 16; off <<= 1) {
                ts[nf][p] += __shfl_xor_sync(0xFFFFFFFFu, ts[nf][p], off);
                tq[nf][p] += __shfl_xor_sync(0xFFFFFFFFu, tq[nf][p], off);
            }
        }
    }
    if (lane < 4) {
#pragma unroll
        for (int nf = 0; nf < 4; nf++) {
            int col = nTile * 128 + n0 + nf * 8 + tg * 2;
            atomicAdd(&st[col],            ts[nf][0]);
            atomicAdd(&st[col + 1],        ts[nf][1]);
            atomicAdd(&st[COUT + col],     tq[nf][0]);
            atomicAdd(&st[COUT + col + 1], tq[nf][1]);
        }
    }
}

// ---------------------------------------------------------------------------
// fp16-A HMMA GEMM: A fp16 single, B fp16 hi/lo split; 2 MMAs per fragment.
// Ntot = 128 fixed (nTile = 0). Stage (48KB): A[16K] Bh[16K] Bl[16K], 3 stages.
// OUT 0: split bf16 output (for GEMM3 A). OUT 1: fp16 single output (+bias).
// ---------------------------------------------------------------------------
#define STAGE_F16 49152

__device__ __forceinline__ void issue_chunk_f16(
    const f16* gA, const f16* gBh, const f16* gBl,
    int K, int c, uint32_t sb, int tid)
{
    const int kt = c * 64;
#pragma unroll
    for (int i = 0; i < 4; i++) {
        int idx = tid + i * 256;
        int r = idx >> 3, ch = idx & 7;
        uint32_t off = (uint32_t)(r * 128 + ((ch ^ (r & 7)) << 4));
        cpa16(sb + off, gA + (size_t)r * K + kt + ch * 8);
    }
#pragma unroll
    for (int i = 0; i < 4; i++) {
        int idx = tid + i * 256;
        int r = idx >> 4, ch = idx & 15;
        uint32_t off = (uint32_t)(r * 256 + ((ch ^ (r & 7)) << 4));
        size_t go = (size_t)(kt + r) * CMID + ch * 8;
        cpa16(sb + 16384 + off, gBh + go);
        cpa16(sb + 32768 + off, gBl + go);
    }
    cp_commit();
}

template <int OUT>
__global__ void __launch_bounds__(256)
mma_gemm_f16A(const f16* __restrict__ A, const f16* __restrict__ Bh,
              const f16* __restrict__ Bl, const float* __restrict__ bias,
              bf16* __restrict__ Ch, bf16* __restrict__ Cl,
              f16* __restrict__ Cs, int K)
{
    extern __shared__ char smem[];
    const uint32_t sb0 = s2u(smem);

    const int tid  = threadIdx.x;
    const int wid  = tid >> 5;
    const int lane = tid & 31;
    const int z     = blockIdx.z;
    const int mTile = blockIdx.y;

    const int m0 = (wid & 1) * 64;
    const int n0 = (wid >> 1) * 32;

    const size_t brA = (size_t)z * NPTS * K;
    const size_t brC = (size_t)z * NPTS * CMID;
    const f16* gA = A + brA + (size_t)mTile * 128 * K;

    float acc[4][4][4];
#pragma unroll
    for (int i = 0; i < 4; i++)
#pragma unroll
        for (int j = 0; j < 4; j++)
#pragma unroll
            for (int t = 0; t < 4; t++) acc[i][j][t] = 0.0f;

    const int nch = K >> 6;
    issue_chunk_f16(gA, Bh, Bl, K, 0, sb0, tid);
    if (nch > 1)
        issue_chunk_f16(gA, Bh, Bl, K, 1, sb0 + STAGE_F16, tid);
    else
        cp_commit();

    int bufn = 2 % 3;
    for (int c = 0; c < nch; c++) {
        if (c + 2 < nch)
            issue_chunk_f16(gA, Bh, Bl, K, c + 2, sb0 + bufn * STAGE_F16, tid);
        else
            cp_commit();
        bufn = bufn == 2 ? 0 : bufn + 1;
        cp_wait<2>();
        __syncthreads();

        const uint32_t sb = sb0 + (c % 3) * STAGE_F16;
        const uint32_t sA = sb, sB = sb + 16384;

#pragma unroll
        for (int ks = 0; ks < 4; ks++) {
            uint32_t bh[4][2], bl[4][2];
#pragma unroll
            for (int pr = 0; pr < 2; pr++) {
                int k   = ks * 16 + (lane & 15);
                int chn = ((n0 + pr * 16) >> 3) + (lane >> 4);
                uint32_t ba = sB + (uint32_t)(k * 256 + ((chn ^ (k & 7)) << 4));
                uint32_t t[4];
                ldsm4t(t, ba);
                bh[pr * 2][0] = t[0]; bh[pr * 2][1] = t[1];
                bh[pr * 2 + 1][0] = t[2]; bh[pr * 2 + 1][1] = t[3];
                ldsm4t(t, ba + 16384);
                bl[pr * 2][0] = t[0]; bl[pr * 2][1] = t[1];
                bl[pr * 2 + 1][0] = t[2]; bl[pr * 2 + 1][1] = t[3];
            }
#pragma unroll
            for (int mf = 0; mf < 4; mf++) {
                int r   = m0 + mf * 16 + (lane & 15);
                int chk = ks * 2 + (lane >> 4);
                uint32_t aa = sA + (uint32_t)(r * 128 + ((chk ^ (r & 7)) << 4));
                uint32_t av[4];
                ldsm4(av, aa);
#pragma unroll
                for (int nf = 0; nf < 4; nf++) {
                    mma_hf(acc[mf][nf], av, bh[nf]);
                    mma_hf(acc[mf][nf], av, bl[nf]);
                }
            }
        }
        __syncthreads();
    }

    const int g  = lane >> 2;
    const int tg = lane & 3;
#pragma unroll
    for (int mf = 0; mf < 4; mf++) {
#pragma unroll
        for (int nf = 0; nf < 4; nf++) {
            int col = n0 + nf * 8 + tg * 2;
            float b0 = (OUT == 1) ? bias[col] : 0.0f;
            float b1 = (OUT == 1) ? bias[col + 1] : 0.0f;
#pragma unroll
            for (int hrow = 0; hrow < 2; hrow++) {
                int row = mTile * 128 + m0 + mf * 16 + g + hrow * 8;
                float v0 = acc[mf][nf][hrow * 2 + 0] + b0;
                float v1 = acc[mf][nf][hrow * 2 + 1] + b1;
                size_t o = brC + (size_t)row * CMID + col;
                if (OUT == 1) {
                    __half2 p = __floats2half2_rn(v0, v1);
                    *reinterpret_cast<__half2*>(Cs + o) = p;
                } else {
                    bf16 h0, l0, h1, l1;
                    split_f32(v0, h0, l0);
                    split_f32(v1, h1, l1);
                    bf162 hp; hp.x = h0; hp.y = h1;
                    bf162 lp; lp.x = l0; lp.y = l1;
                    *reinterpret_cast<bf162*>(Ch + o) = hp;
                    *reinterpret_cast<bf162*>(Cl + o) = lp;
                }
            }
        }
    }
}

// ---------------------------------------------------------------------------
// Conversions
// ---------------------------------------------------------------------------
__global__ void __launch_bounds__(256)
conv_act_f16(const float* __restrict__ a0, const float* __restrict__ a1,
             f16* __restrict__ o, int n4)
{
    const int z = blockIdx.y;
    const float* a = z ? a1 : a0;
    const size_t off = (size_t)z * n4;
    int i = blockIdx.x * 256 + threadIdx.x;
    if (i < n4) {
        float4 v = reinterpret_cast<const float4*>(a)[i];
        __half2 p0 = __floats2half2_rn(v.x, v.y);
        __half2 p1 = __floats2half2_rn(v.z, v.w);
        uint2 pk;
        pk.x = *reinterpret_cast<uint32_t*>(&p0);
        pk.y = *reinterpret_cast<uint32_t*>(&p1);
        reinterpret_cast<uint2*>(o)[off + i] = pk;
    }
}

__global__ void __launch_bounds__(256)
split_w_bf(const float* __restrict__ in, bf16* __restrict__ oh, bf16* __restrict__ ol, int n)
{
    int i = blockIdx.x * 256 + threadIdx.x;
    if (i < n) {
        bf16 h, l;
        split_f32(in[i], h, l);
        oh[i] = h;
        ol[i] = l;
    }
}

__global__ void __launch_bounds__(256)
split_w_f16(const float* __restrict__ in, f16* __restrict__ oh, f16* __restrict__ ol, int n)
{
    int i = blockIdx.x * 256 + threadIdx.x;
    if (i < n) {
        float v = in[i];
        f16 h = __float2half(v);
        oh[i] = h;
        ol[i] = __float2half(v - __half2float(h));
    }
}

// ---------------------------------------------------------------------------
// KPConv aggregation, f32x2 packed-FMA version.
// 128-thread CTA handles 2 points. Thread u in [0,64) of each point handles
// channel pair (2u, 2u+1). Inner loop: 1 LDS.64 (packed infl) + 1 FFMA2.
// ---------------------------------------------------------------------------
__global__ void __launch_bounds__(128)
kpconv_agg2(const f16* __restrict__ hbuf,
            const float* __restrict__ coords0, const float* __restrict__ coords1,
            const int* __restrict__ neighb0, const int* __restrict__ neighb1,
            const float* __restrict__ kpts, f16* __restrict__ agg)
{
    const int z = blockIdx.z;
    const float* coords = z ? coords1 : coords0;
    const int*   neighb = z ? neighb1 : neighb0;
    const size_t brH = (size_t)z * NPTS * CMID;
    const size_t brA = (size_t)z * NPTS * PC;

    const int t   = threadIdx.x;
    const int pt  = t >> 6;              // 0 or 1: which point in this CTA
    const int u   = t & 63;              // channel-pair index
    const int n   = blockIdx.x * 2 + pt;

    __shared__ int   nb_s[2][KNB];
    __shared__ float rel_s[2][KNB][3];
    __shared__ __align__(8) ull ipack[2][KNB][16];   // {infl,infl} packed

    if (u < KNB) nb_s[pt][u] = neighb[n * KNB + u];
    __syncthreads();
    // rel: 96 values per point over 64 threads -> strided loop (BUGFIX)
    for (int idx = u; idx < KNB * 3; idx += 64) {
        int k = idx / 3, d = idx % 3;
        rel_s[pt][k][d] = coords[(size_t)nb_s[pt][k] * 3 + d]
                        - coords[(size_t)n * 3 + d];
    }
    __syncthreads();
    for (int idx = u; idx < KNB * PKP; idx += 64) {
        int k = idx / PKP, p = idx % PKP;
        float dx = rel_s[pt][k][0] - kpts[p * 3 + 0];
        float dy = rel_s[pt][k][1] - kpts[p * 3 + 1];
        float dz = rel_s[pt][k][2] - kpts[p * 3 + 2];
        float d  = sqrtf(dx * dx + dy * dy + dz * dz);
        float iv = fmaxf(0.0f, 1.0f - d * 1.25f);   // EXTENT = 0.8
        ipack[pt][k][p] = pack2(iv, iv);
    }
    __syncthreads();

    ull acc2[PKP];
#pragma unroll
    for (int p = 0; p < PKP; p++) acc2[p] = 0ull;

    const int ch2 = u;   // half2 index: channels (2u, 2u+1)
#pragma unroll 2
    for (int k = 0; k < KNB; k++) {
        __half2 hv = __ldg(reinterpret_cast<const __half2*>(
            hbuf + brH + (size_t)nb_s[pt][k] * CMID) + ch2);
        float2 f = __half22float2(hv);
        ull av = pack2(f.x, f.y);
        const ull* ip = ipack[pt][k];
#pragma unroll
        for (int p = 0; p < PKP; p++)
            fma2(acc2[p], av, ip[p]);
    }

    f16* o = agg + brA + (size_t)n * PC;
#pragma unroll
    for (int p = 0; p < PKP; p++) {
        float x, y;
        unpack2(acc2[p], x, y);
        __half2 hv = __floats2half2_rn(x, y);
        reinterpret_cast<__half2*>(o + (size_t)p * CMID)[ch2] = hv;
    }
}

// ---------------------------------------------------------------------------
// BatchNorm apply (stats accumulated by GEMM3 epilogue)
// ---------------------------------------------------------------------------
__global__ void zero_stats(float* s)
{
    s[blockIdx.x * 1024 + threadIdx.x] = 0.0f;   // <<<2, 1024>>>
}

__global__ void __launch_bounds__(256)
bn_apply4(const float* __restrict__ ybase, const float* __restrict__ stats,
          const float* __restrict__ gamma, const float* __restrict__ beta,
          float* __restrict__ outbase)
{
    const int z = blockIdx.y;
    const float* y   = ybase + (size_t)z * NPTS * COUT;
    const float* st  = stats + (size_t)z * 2 * COUT;
    float*       out = outbase + (size_t)z * NPTS * COUT;

    const int i = blockIdx.x * blockDim.x + threadIdx.x;
    const int c = (i * 4) & (COUT - 1);
    float4 v = reinterpret_cast<const float4*>(y)[i];
    float r[4] = {v.x, v.y, v.z, v.w};
#pragma unroll
    for (int j = 0; j < 4; j++) {
        float mu  = st[c + j] * (1.0f / NPTS);
        float var = st[COUT + c + j] * (1.0f / NPTS) - mu * mu;
        float scale = rsqrtf(var + 1e-5f) * gamma[c + j];
        float t = (r[j] - mu) * scale + beta[c + j];
        r[j] = (t >= 0.0f) ? t : 0.1f * t;
    }
    reinterpret_cast<float4*>(out)[i] = make_float4(r[0], r[1], r[2], r[3]);
}

__global__ void copy_coords(const float* __restrict__ a, const float* __restrict__ b,
                            float* __restrict__ out)
{
    int i = blockIdx.x * blockDim.x + threadIdx.x;
    if (i < NPTS * 3) {
        out[i]            = a[i];
        out[NPTS * 3 + i] = b[i];
    }
}

// ---------------------------------------------------------------------------
// Launcher
// ---------------------------------------------------------------------------
#define SMEM_DYN  (3 * STAGE_BYTES)
#define SMEM_DYN2 (3 * STAGE_F16)

extern "C" void kernel_launch(void* const* d_in, const int* in_sizes, int n_in,
                              void* d_out, int out_size)
{
    (void)in_sizes; (void)n_in; (void)out_size;

    const float* src    = (const float*)d_in[0];
    const float* tgt    = (const float*)d_in[1];
    const float* sc     = (const float*)d_in[2];
    const float* tc     = (const float*)d_in[3];
    const int*   snb    = (const int*)  d_in[4];
    const int*   tnb    = (const int*)  d_in[5];
    const float* W_in   = (const float*)d_in[6];
    const float* b_in   = (const float*)d_in[7];
    const float* kpts   = (const float*)d_in[8];
    const float* kpw    = (const float*)d_in[9];
    const float* W_out  = (const float*)d_in[10];
    const float* b_out  = (const float*)d_in[11];
    const float* gamma  = (const float*)d_in[12];
    const float* beta   = (const float*)d_in[13];
    float* out = (float*)d_out;

    f16 *xs, *h, *ag, *wi_h, *wi_l, *kw_h, *kw_l;
    bf16 *md_h, *md_l, *wo_h, *wo_l;
    float *y, *stats;
    cudaGetSymbolAddress((void**)&xs,   g_xs);
    cudaGetSymbolAddress((void**)&h,    g_h);
    cudaGetSymbolAddress((void**)&ag,   g_ag);
    cudaGetSymbolAddress((void**)&md_h, g_md_h);  cudaGetSymbolAddress((void**)&md_l, g_md_l);
    cudaGetSymbolAddress((void**)&wi_h, g_wi_h);  cudaGetSymbolAddress((void**)&wi_l, g_wi_l);
    cudaGetSymbolAddress((void**)&kw_h, g_kw_h);  cudaGetSymbolAddress((void**)&kw_l, g_kw_l);
    cudaGetSymbolAddress((void**)&wo_h, g_wo_h);  cudaGetSymbolAddress((void**)&wo_l, g_wo_l);
    cudaGetSymbolAddress((void**)&y, g_y);
    cudaGetSymbolAddress((void**)&stats, g_stats);

    cudaFuncSetAttribute(mma_gemm_bn,      cudaFuncAttributeMaxDynamicSharedMemorySize, SMEM_DYN);
    cudaFuncSetAttribute(mma_gemm_f16A<0>, cudaFuncAttributeMaxDynamicSharedMemorySize, SMEM_DYN2);
    cudaFuncSetAttribute(mma_gemm_f16A<1>, cudaFuncAttributeMaxDynamicSharedMemorySize, SMEM_DYN2);

    // Weight preps
    split_w_f16<<<(CIN * CMID + 255) / 256, 256>>>(W_in, wi_h, wi_l, CIN * CMID);
    split_w_f16<<<(PC * CMID + 255) / 256, 256>>>(kpw, kw_h, kw_l, PC * CMID);
    split_w_bf<<<(CMID * COUT + 255) / 256, 256>>>(W_out, wo_h, wo_l, CMID * COUT);

    // Inputs -> fp16 single (both branches)
    conv_act_f16<<<dim3((NPTS * CIN / 4 + 255) / 256, 2), 256>>>(
        src, tgt, xs, NPTS * CIN / 4);

    // Zero BN stats (consumed by GEMM3 epilogue atomics)
    zero_stats<<<2, 1024>>>(stats);

    // GEMM1: h = x @ W_in + b_in -> fp16 single
    mma_gemm_f16A<1><<<dim3(1, NPTS / 128, 2), 256, SMEM_DYN2>>>(
        xs, wi_h, wi_l, b_in, nullptr, nullptr, h, CIN);

    // KPConv gather + aggregation -> agg fp16 [16384, 1920]
    kpconv_agg2<<<dim3(NPTS / 2, 1, 2), 128>>>(h, sc, tc, snb, tnb, kpts, ag);

    // mid = agg @ kpw (A fp16, B fp16 split) -> split bf16
    mma_gemm_f16A<0><<<dim3(1, NPTS / 128, 2), 256, SMEM_DYN2>>>(
        ag, kw_h, kw_l, nullptr, md_h, md_l, nullptr, PC);

    // y = mid @ W_out + b_out -> fp32 + fused BN stats
    mma_gemm_bn<<<dim3(COUT / 128, NPTS / 128, 2), 256, SMEM_DYN>>>(
        md_h, md_l, wo_h, wo_l, b_out, y, stats, CMID, COUT);

    // BN normalize + LeakyReLU
    bn_apply4<<<dim3((NPTS * COUT / 4) / 256, 2), 256>>>(y, stats, gamma, beta, out);

    // coords pass-through
    copy_coords<<<(NPTS * 3 + 255) / 256, 256>>>(sc, tc, out + 2ull * NPTS * COUT);
}

// round 9
// speedup vs baseline: 2.9558x; 1.1677x over previous
#include <cuda_runtime.h>
#include <cuda_bf16.h>
#include <cuda_fp16.h>
#include <math.h>
#include <stdint.h>

#define NPTS 16384
#define KNB  32
#define PKP  15
#define CIN  256
#define CMID 128
#define COUT 512
#define PC   (PKP * CMID)   // 1920

typedef unsigned long long ull;
typedef __half f16;

// ---------------------------------------------------------------------------
// Scratch (device globals -- allocation-free)
// ---------------------------------------------------------------------------
__device__ __align__(128) f16   g_xs  [2ull * NPTS * CIN];                  // fp16
__device__ __align__(128) f16   g_h   [2ull * NPTS * CMID];                 // fp16
__device__ __align__(128) f16   g_ag  [2ull * NPTS * PC];                   // fp16
__device__ __align__(128) f16   g_md  [2ull * NPTS * CMID];                 // fp16
__device__ __align__(128) float g_y   [2ull * NPTS * COUT];
__device__ __align__(128) f16   g_wi_h[CIN * CMID],  g_wi_l[CIN * CMID];    // split
__device__ __align__(128) f16   g_kw  [PC * CMID];                          // single
__device__ __align__(128) f16   g_wo_h[CMID * COUT], g_wo_l[CMID * COUT];   // split
__device__ float g_stats[2 * 2 * COUT];

// ---------------------------------------------------------------------------
// PTX helpers
// ---------------------------------------------------------------------------
__device__ __forceinline__ uint32_t s2u(const void* p)
{
    return (uint32_t)__cvta_generic_to_shared(p);
}
__device__ __forceinline__ void cpa16(uint32_t s, const void* g)
{
    asm volatile("cp.async.cg.shared.global [%0], [%1], 16;" :: "r"(s), "l"(g));
}
__device__ __forceinline__ void cp_commit()
{
    asm volatile("cp.async.commit_group;" ::: "memory");
}
template <int N>
__device__ __forceinline__ void cp_wait()
{
    asm volatile("cp.async.wait_group %0;" :: "n"(N) : "memory");
}
__device__ __forceinline__ void ldsm4(uint32_t* r, uint32_t a)
{
    asm volatile("ldmatrix.sync.aligned.m8n8.x4.shared.b16 {%0,%1,%2,%3}, [%4];"
                 : "=r"(r[0]), "=r"(r[1]), "=r"(r[2]), "=r"(r[3]) : "r"(a));
}
__device__ __forceinline__ void ldsm4t(uint32_t* r, uint32_t a)
{
    asm volatile("ldmatrix.sync.aligned.m8n8.x4.trans.shared.b16 {%0,%1,%2,%3}, [%4];"
                 : "=r"(r[0]), "=r"(r[1]), "=r"(r[2]), "=r"(r[3]) : "r"(a));
}
__device__ __forceinline__ void mma_hf(float* c, const uint32_t* a, const uint32_t* b)
{
    asm volatile(
        "mma.sync.aligned.m16n8k16.row.col.f32.f16.f16.f32 "
        "{%0,%1,%2,%3}, {%4,%5,%6,%7}, {%8,%9}, {%0,%1,%2,%3};"
        : "+f"(c[0]), "+f"(c[1]), "+f"(c[2]), "+f"(c[3])
        : "r"(a[0]), "r"(a[1]), "r"(a[2]), "r"(a[3]), "r"(b[0]), "r"(b[1]));
}
__device__ __forceinline__ void fma2(ull& d, ull a, ull b)
{
    asm("fma.rn.f32x2 %0, %1, %2, %0;" : "+l"(d) : "l"(a), "l"(b));
}
__device__ __forceinline__ ull pack2(float x, float y)
{
    ull r;
    asm("mov.b64 %0, {%1, %2};" : "=l"(r) : "f"(x), "f"(y));
    return r;
}
__device__ __forceinline__ void unpack2(ull v, float& x, float& y)
{
    asm("mov.b64 {%0, %1}, %2;" : "=f"(x), "=f"(y) : "l"(v));
}

// ---------------------------------------------------------------------------
// Unified fp16 HMMA GEMM. A fp16 single; B fp16 single (BSPLIT=0) or hi/lo
// split (BSPLIT=1, 2 MMAs). CTA tile 128x128, BK=64, 8 warps (2m x 4n),
// warp tile 64x32. 3-stage cp.async pipeline.
// Stage: A[16K] + B[16K or 32K].
// OUT 0: fp16 out (+bias if non-null).
// OUT 1: fp32 out (+bias) AND per-channel BN stats via atomics.
// blockIdx = (nTile, mTile, branch)
// ---------------------------------------------------------------------------
template <int BSPLIT>
__device__ __forceinline__ void issue_hg(
    const f16* gA, const f16* gBh, const f16* gBl,
    int K, int Ntot, int c, uint32_t sb, int tid)
{
    const int kt = c * 64;
#pragma unroll
    for (int i = 0; i < 4; i++) {
        int idx = tid + i * 256;            // A: 128 rows x 8 16B-chunks
        int r = idx >> 3, ch = idx & 7;
        uint32_t off = (uint32_t)(r * 128 + ((ch ^ (r & 7)) << 4));
        cpa16(sb + off, gA + (size_t)r * K + kt + ch * 8);
    }
#pragma unroll
    for (int i = 0; i < 4; i++) {
        int idx = tid + i * 256;            // B: 64 rows x 16 16B-chunks
        int r = idx >> 4, ch = idx & 15;
        uint32_t off = (uint32_t)(r * 256 + ((ch ^ (r & 7)) << 4));
        size_t go = (size_t)(kt + r) * Ntot + ch * 8;
        cpa16(sb + 16384 + off, gBh + go);
        if (BSPLIT) cpa16(sb + 32768 + off, gBl + go);
    }
    cp_commit();
}

template <int BSPLIT, int OUT>
__global__ void __launch_bounds__(256)
hgemm(const f16* __restrict__ A, const f16* __restrict__ Bh,
      const f16* __restrict__ Bl, const float* __restrict__ bias,
      f16* __restrict__ Cs, float* __restrict__ Cf, float* __restrict__ stats,
      int K, int Ntot)
{
    constexpr int STAGE = 16384 + (BSPLIT ? 32768 : 16384);
    extern __shared__ char smem[];
    const uint32_t sb0 = s2u(smem);

    const int tid  = threadIdx.x;
    const int wid  = tid >> 5;
    const int lane = tid & 31;
    const int z     = blockIdx.z;
    const int mTile = blockIdx.y;
    const int nTile = blockIdx.x;

    const int m0 = (wid & 1) * 64;
    const int n0 = (wid >> 1) * 32;

    const size_t brA = (size_t)z * NPTS * K;
    const size_t brC = (size_t)z * NPTS * Ntot;
    const f16* gA  = A + brA + (size_t)mTile * 128 * K;
    const f16* gBh = Bh + (size_t)nTile * 128;
    const f16* gBl = BSPLIT ? Bl + (size_t)nTile * 128 : nullptr;

    float acc[4][4][4];
#pragma unroll
    for (int i = 0; i < 4; i++)
#pragma unroll
        for (int j = 0; j < 4; j++)
#pragma unroll
            for (int t = 0; t < 4; t++) acc[i][j][t] = 0.0f;

    const int nch = K >> 6;
    issue_hg<BSPLIT>(gA, gBh, gBl, K, Ntot, 0, sb0, tid);
    if (nch > 1)
        issue_hg<BSPLIT>(gA, gBh, gBl, K, Ntot, 1, sb0 + STAGE, tid);
    else
        cp_commit();

    int bufn = 2 % 3;
    for (int c = 0; c < nch; c++) {
        if (c + 2 < nch)
            issue_hg<BSPLIT>(gA, gBh, gBl, K, Ntot, c + 2,
                             sb0 + bufn * STAGE, tid);
        else
            cp_commit();
        bufn = bufn == 2 ? 0 : bufn + 1;
        cp_wait<2>();
        __syncthreads();

        const uint32_t sb = sb0 + (c % 3) * STAGE;
        const uint32_t sA = sb, sB = sb + 16384;

#pragma unroll
        for (int ks = 0; ks < 4; ks++) {
            uint32_t bh[4][2], bl[4][2];
#pragma unroll
            for (int pr = 0; pr < 2; pr++) {
                int k   = ks * 16 + (lane & 15);
                int chn = ((n0 + pr * 16) >> 3) + (lane >> 4);
                uint32_t ba = sB + (uint32_t)(k * 256 + ((chn ^ (k & 7)) << 4));
                uint32_t t[4];
                ldsm4t(t, ba);
                bh[pr * 2][0] = t[0]; bh[pr * 2][1] = t[1];
                bh[pr * 2 + 1][0] = t[2]; bh[pr * 2 + 1][1] = t[3];
                if (BSPLIT) {
                    ldsm4t(t, ba + 16384);
                    bl[pr * 2][0] = t[0]; bl[pr * 2][1] = t[1];
                    bl[pr * 2 + 1][0] = t[2]; bl[pr * 2 + 1][1] = t[3];
                }
            }
#pragma unroll
            for (int mf = 0; mf < 4; mf++) {
                int r   = m0 + mf * 16 + (lane & 15);
                int chk = ks * 2 + (lane >> 4);
                uint32_t aa = sA + (uint32_t)(r * 128 + ((chk ^ (r & 7)) << 4));
                uint32_t av[4];
                ldsm4(av, aa);
#pragma unroll
                for (int nf = 0; nf < 4; nf++) {
                    mma_hf(acc[mf][nf], av, bh[nf]);
                    if (BSPLIT) mma_hf(acc[mf][nf], av, bl[nf]);
                }
            }
        }
        __syncthreads();
    }

    const int g  = lane >> 2;
    const int tg = lane & 3;

    float ts[4][2], tq[4][2];
    if (OUT == 1) {
#pragma unroll
        for (int nf = 0; nf < 4; nf++)
            ts[nf][0] = ts[nf][1] = tq[nf][0] = tq[nf][1] = 0.0f;
    }

#pragma unroll
    for (int mf = 0; mf < 4; mf++) {
#pragma unroll
        for (int nf = 0; nf < 4; nf++) {
            int col = nTile * 128 + n0 + nf * 8 + tg * 2;
            float b0 = bias ? bias[col] : 0.0f;
            float b1 = bias ? bias[col + 1] : 0.0f;
#pragma unroll
            for (int hrow = 0; hrow < 2; hrow++) {
                int row = mTile * 128 + m0 + mf * 16 + g + hrow * 8;
                float v0 = acc[mf][nf][hrow * 2 + 0] + b0;
                float v1 = acc[mf][nf][hrow * 2 + 1] + b1;
                size_t o = brC + (size_t)row * Ntot + col;
                if (OUT == 1) {
                    *reinterpret_cast<float2*>(Cf + o) = make_float2(v0, v1);
                    ts[nf][0] += v0;  tq[nf][0] = fmaf(v0, v0, tq[nf][0]);
                    ts[nf][1] += v1;  tq[nf][1] = fmaf(v1, v1, tq[nf][1]);
                } else {
                    __half2 p = __floats2half2_rn(v0, v1);
                    *reinterpret_cast<__half2*>(Cs + o) = p;
                }
            }
        }
    }

    if (OUT == 1) {
        float* st = stats + (size_t)z * 2 * COUT;
#pragma unroll
        for (int nf = 0; nf < 4; nf++) {
#pragma unroll
            for (int p = 0; p < 2; p++) {
#pragma unroll
                for (int off = 4; off <= 16; off <<= 1) {
                    ts[nf][p] += __shfl_xor_sync(0xFFFFFFFFu, ts[nf][p], off);
                    tq[nf][p] += __shfl_xor_sync(0xFFFFFFFFu, tq[nf][p], off);
                }
            }
        }
        if (lane < 4) {
#pragma unroll
            for (int nf = 0; nf < 4; nf++) {
                int col = nTile * 128 + n0 + nf * 8 + tg * 2;
                atomicAdd(&st[col],            ts[nf][0]);
                atomicAdd(&st[col + 1],        ts[nf][1]);
                atomicAdd(&st[COUT + col],     tq[nf][0]);
                atomicAdd(&st[COUT + col + 1], tq[nf][1]);
            }
        }
    }
}

// ---------------------------------------------------------------------------
// Conversions
// ---------------------------------------------------------------------------
__global__ void __launch_bounds__(256)
conv_act_f16(const float* __restrict__ a0, const float* __restrict__ a1,
             f16* __restrict__ o, int n4)
{
    const int z = blockIdx.y;
    const float* a = z ? a1 : a0;
    const size_t off = (size_t)z * n4;
    int i = blockIdx.x * 256 + threadIdx.x;
    if (i < n4) {
        float4 v = reinterpret_cast<const float4*>(a)[i];
        __half2 p0 = __floats2half2_rn(v.x, v.y);
        __half2 p1 = __floats2half2_rn(v.z, v.w);
        uint2 pk;
        pk.x = *reinterpret_cast<uint32_t*>(&p0);
        pk.y = *reinterpret_cast<uint32_t*>(&p1);
        reinterpret_cast<uint2*>(o)[off + i] = pk;
    }
}

__global__ void __launch_bounds__(256)
split_w_f16(const float* __restrict__ in, f16* __restrict__ oh, f16* __restrict__ ol, int n)
{
    int i = blockIdx.x * 256 + threadIdx.x;
    if (i < n) {
        float v = in[i];
        f16 h = __float2half(v);
        oh[i] = h;
        if (ol) ol[i] = __float2half(v - __half2float(h));
    }
}

// ---------------------------------------------------------------------------
// KPConv aggregation, f32x2 packed-FMA. 128-thread CTA = 2 points;
// thread u in [0,64) handles channel pair (2u, 2u+1).
// Inner loop: 1 LDG.32 gather + 1 LDS.64 infl + 1 FFMA2 per (k,p).
// ---------------------------------------------------------------------------
__global__ void __launch_bounds__(128)
kpconv_agg2(const f16* __restrict__ hbuf,
            const float* __restrict__ coords0, const float* __restrict__ coords1,
            const int* __restrict__ neighb0, const int* __restrict__ neighb1,
            const float* __restrict__ kpts, f16* __restrict__ agg)
{
    const int z = blockIdx.z;
    const float* coords = z ? coords1 : coords0;
    const int*   neighb = z ? neighb1 : neighb0;
    const size_t brH = (size_t)z * NPTS * CMID;
    const size_t brA = (size_t)z * NPTS * PC;

    const int t   = threadIdx.x;
    const int pt  = t >> 6;
    const int u   = t & 63;
    const int n   = blockIdx.x * 2 + pt;

    __shared__ int   nb_s[2][KNB];
    __shared__ float rel_s[2][KNB][3];
    __shared__ __align__(8) ull ipack[2][KNB][16];

    if (u < KNB) nb_s[pt][u] = neighb[n * KNB + u];
    __syncthreads();
    for (int idx = u; idx < KNB * 3; idx += 64) {
        int k = idx / 3, d = idx % 3;
        rel_s[pt][k][d] = coords[(size_t)nb_s[pt][k] * 3 + d]
                        - coords[(size_t)n * 3 + d];
    }
    __syncthreads();
    for (int idx = u; idx < KNB * PKP; idx += 64) {
        int k = idx / PKP, p = idx % PKP;
        float dx = rel_s[pt][k][0] - kpts[p * 3 + 0];
        float dy = rel_s[pt][k][1] - kpts[p * 3 + 1];
        float dz = rel_s[pt][k][2] - kpts[p * 3 + 2];
        float d  = sqrtf(dx * dx + dy * dy + dz * dz);
        float iv = fmaxf(0.0f, 1.0f - d * 1.25f);   // EXTENT = 0.8
        ipack[pt][k][p] = pack2(iv, iv);
    }
    __syncthreads();

    ull acc2[PKP];
#pragma unroll
    for (int p = 0; p < PKP; p++) acc2[p] = 0ull;

    const int ch2 = u;
#pragma unroll 2
    for (int k = 0; k < KNB; k++) {
        __half2 hv = __ldg(reinterpret_cast<const __half2*>(
            hbuf + brH + (size_t)nb_s[pt][k] * CMID) + ch2);
        float2 f = __half22float2(hv);
        ull av = pack2(f.x, f.y);
        const ull* ip = ipack[pt][k];
#pragma unroll
        for (int p = 0; p < PKP; p++)
            fma2(acc2[p], av, ip[p]);
    }

    f16* o = agg + brA + (size_t)n * PC;
#pragma unroll
    for (int p = 0; p < PKP; p++) {
        float x, y;
        unpack2(acc2[p], x, y);
        __half2 hv = __floats2half2_rn(x, y);
        reinterpret_cast<__half2*>(o + (size_t)p * CMID)[ch2] = hv;
    }
}

// ---------------------------------------------------------------------------
// BatchNorm apply
// ---------------------------------------------------------------------------
__global__ void zero_stats(float* s)
{
    s[blockIdx.x * 1024 + threadIdx.x] = 0.0f;   // <<<2, 1024>>>
}

__global__ void __launch_bounds__(256)
bn_apply4(const float* __restrict__ ybase, const float* __restrict__ stats,
          const float* __restrict__ gamma, const float* __restrict__ beta,
          float* __restrict__ outbase)
{
    const int z = blockIdx.y;
    const float* y   = ybase + (size_t)z * NPTS * COUT;
    const float* st  = stats + (size_t)z * 2 * COUT;
    float*       out = outbase + (size_t)z * NPTS * COUT;

    const int i = blockIdx.x * blockDim.x + threadIdx.x;
    const int c = (i * 4) & (COUT - 1);
    float4 v = reinterpret_cast<const float4*>(y)[i];
    float r[4] = {v.x, v.y, v.z, v.w};
#pragma unroll
    for (int j = 0; j < 4; j++) {
        float mu  = st[c + j] * (1.0f / NPTS);
        float var = st[COUT + c + j] * (1.0f / NPTS) - mu * mu;
        float scale = rsqrtf(var + 1e-5f) * gamma[c + j];
        float t = (r[j] - mu) * scale + beta[c + j];
        r[j] = (t >= 0.0f) ? t : 0.1f * t;
    }
    reinterpret_cast<float4*>(out)[i] = make_float4(r[0], r[1], r[2], r[3]);
}

__global__ void copy_coords(const float* __restrict__ a, const float* __restrict__ b,
                            float* __restrict__ out)
{
    int i = blockIdx.x * blockDim.x + threadIdx.x;
    if (i < NPTS * 3) {
        out[i]            = a[i];
        out[NPTS * 3 + i] = b[i];
    }
}

// ---------------------------------------------------------------------------
// Launcher
// ---------------------------------------------------------------------------
#define SMEM_SPLIT  (3 * 49152)   // BSPLIT=1 stage 48KB
#define SMEM_SINGLE (3 * 32768)   // BSPLIT=0 stage 32KB

extern "C" void kernel_launch(void* const* d_in, const int* in_sizes, int n_in,
                              void* d_out, int out_size)
{
    (void)in_sizes; (void)n_in; (void)out_size;

    const float* src    = (const float*)d_in[0];
    const float* tgt    = (const float*)d_in[1];
    const float* sc     = (const float*)d_in[2];
    const float* tc     = (const float*)d_in[3];
    const int*   snb    = (const int*)  d_in[4];
    const int*   tnb    = (const int*)  d_in[5];
    const float* W_in   = (const float*)d_in[6];
    const float* b_in   = (const float*)d_in[7];
    const float* kpts   = (const float*)d_in[8];
    const float* kpw    = (const float*)d_in[9];
    const float* W_out  = (const float*)d_in[10];
    const float* b_out  = (const float*)d_in[11];
    const float* gamma  = (const float*)d_in[12];
    const float* beta   = (const float*)d_in[13];
    float* out = (float*)d_out;

    f16 *xs, *h, *ag, *md, *wi_h, *wi_l, *kw, *wo_h, *wo_l;
    float *y, *stats;
    cudaGetSymbolAddress((void**)&xs,   g_xs);
    cudaGetSymbolAddress((void**)&h,    g_h);
    cudaGetSymbolAddress((void**)&ag,   g_ag);
    cudaGetSymbolAddress((void**)&md,   g_md);
    cudaGetSymbolAddress((void**)&wi_h, g_wi_h);  cudaGetSymbolAddress((void**)&wi_l, g_wi_l);
    cudaGetSymbolAddress((void**)&kw,   g_kw);
    cudaGetSymbolAddress((void**)&wo_h, g_wo_h);  cudaGetSymbolAddress((void**)&wo_l, g_wo_l);
    cudaGetSymbolAddress((void**)&y, g_y);
    cudaGetSymbolAddress((void**)&stats, g_stats);

    cudaFuncSetAttribute((const void*)hgemm<1, 0>,
                         cudaFuncAttributeMaxDynamicSharedMemorySize, SMEM_SPLIT);
    cudaFuncSetAttribute((const void*)hgemm<0, 0>,
                         cudaFuncAttributeMaxDynamicSharedMemorySize, SMEM_SINGLE);
    cudaFuncSetAttribute((const void*)hgemm<1, 1>,
                         cudaFuncAttributeMaxDynamicSharedMemorySize, SMEM_SPLIT);

    // Weight preps
    split_w_f16<<<(CIN * CMID + 255) / 256, 256>>>(W_in, wi_h, wi_l, CIN * CMID);
    split_w_f16<<<(PC * CMID + 255) / 256, 256>>>(kpw, kw, nullptr, PC * CMID);
    split_w_f16<<<(CMID * COUT + 255) / 256, 256>>>(W_out, wo_h, wo_l, CMID * COUT);

    // Inputs -> fp16 (both branches)
    conv_act_f16<<<dim3((NPTS * CIN / 4 + 255) / 256, 2), 256>>>(
        src, tgt, xs, NPTS * CIN / 4);

    // Zero BN stats
    zero_stats<<<2, 1024>>>(stats);

    // GEMM1: h = x @ W_in + b_in (B split) -> fp16
    hgemm<1, 0><<<dim3(1, NPTS / 128, 2), 256, SMEM_SPLIT>>>(
        xs, wi_h, wi_l, b_in, h, nullptr, nullptr, CIN, CMID);

    // KPConv gather + aggregation -> agg fp16
    kpconv_agg2<<<dim3(NPTS / 2, 1, 2), 128>>>(h, sc, tc, snb, tnb, kpts, ag);

    // mid = agg @ kpw (B single fp16, 1 MMA) -> fp16
    hgemm<0, 0><<<dim3(1, NPTS / 128, 2), 256, SMEM_SINGLE>>>(
        ag, kw, nullptr, nullptr, md, nullptr, nullptr, PC, CMID);

    // y = mid @ W_out + b_out (B split) -> fp32 + fused BN stats
    hgemm<1, 1><<<dim3(COUT / 128, NPTS / 128, 2), 256, SMEM_SPLIT>>>(
        md, wo_h, wo_l, b_out, nullptr, y, stats, CMID, COUT);

    // BN normalize + LeakyReLU
    bn_apply4<<<dim3((NPTS * COUT / 4) / 256, 2), 256>>>(y, stats, gamma, beta, out);

    // coords pass-through
    copy_coords<<<(NPTS * 3 + 255) / 256, 256>>>(sc, tc, out + 2ull * NPTS * COUT);
}

// round 10
// speedup vs baseline: 2.9647x; 1.0030x over previous
#include <cuda_runtime.h>
#include <cuda_bf16.h>
#include <cuda_fp16.h>
#include <math.h>
#include <stdint.h>

#define NPTS 16384
#define KNB  32
#define PKP  15
#define CIN  256
#define CMID 128
#define COUT 512
#define PC   (PKP * CMID)   // 1920

typedef unsigned long long ull;
typedef __half f16;

// ---------------------------------------------------------------------------
// Scratch (device globals -- allocation-free)
// ---------------------------------------------------------------------------
__device__ __align__(128) f16   g_xs  [2ull * NPTS * CIN];                  // fp16
__device__ __align__(128) f16   g_h   [2ull * NPTS * CMID];                 // fp16
__device__ __align__(128) f16   g_ag  [2ull * NPTS * PC];                   // fp16
__device__ __align__(128) f16   g_md  [2ull * NPTS * CMID];                 // fp16
__device__ __align__(128) float g_y   [2ull * NPTS * COUT];
__device__ __align__(128) f16   g_wi_h[CIN * CMID],  g_wi_l[CIN * CMID];    // split
__device__ __align__(128) f16   g_kw  [PC * CMID];                          // single
__device__ __align__(128) f16   g_wo_h[CMID * COUT], g_wo_l[CMID * COUT];   // split
__device__ float g_stats[2 * 2 * COUT];

// ---------------------------------------------------------------------------
// PTX helpers
// ---------------------------------------------------------------------------
__device__ __forceinline__ uint32_t s2u(const void* p)
{
    return (uint32_t)__cvta_generic_to_shared(p);
}
__device__ __forceinline__ void cpa16(uint32_t s, const void* g)
{
    asm volatile("cp.async.cg.shared.global [%0], [%1], 16;" :: "r"(s), "l"(g));
}
__device__ __forceinline__ void cp_commit()
{
    asm volatile("cp.async.commit_group;" ::: "memory");
}
template <int N>
__device__ __forceinline__ void cp_wait()
{
    asm volatile("cp.async.wait_group %0;" :: "n"(N) : "memory");
}
__device__ __forceinline__ void ldsm4(uint32_t* r, uint32_t a)
{
    asm volatile("ldmatrix.sync.aligned.m8n8.x4.shared.b16 {%0,%1,%2,%3}, [%4];"
                 : "=r"(r[0]), "=r"(r[1]), "=r"(r[2]), "=r"(r[3]) : "r"(a));
}
__device__ __forceinline__ void ldsm4t(uint32_t* r, uint32_t a)
{
    asm volatile("ldmatrix.sync.aligned.m8n8.x4.trans.shared.b16 {%0,%1,%2,%3}, [%4];"
                 : "=r"(r[0]), "=r"(r[1]), "=r"(r[2]), "=r"(r[3]) : "r"(a));
}
__device__ __forceinline__ void mma_hf(float* c, const uint32_t* a, const uint32_t* b)
{
    asm volatile(
        "mma.sync.aligned.m16n8k16.row.col.f32.f16.f16.f32 "
        "{%0,%1,%2,%3}, {%4,%5,%6,%7}, {%8,%9}, {%0,%1,%2,%3};"
        : "+f"(c[0]), "+f"(c[1]), "+f"(c[2]), "+f"(c[3])
        : "r"(a[0]), "r"(a[1]), "r"(a[2]), "r"(a[3]), "r"(b[0]), "r"(b[1]));
}
__device__ __forceinline__ void fma2(ull& d, ull a, ull b)
{
    asm("fma.rn.f32x2 %0, %1, %2, %0;" : "+l"(d) : "l"(a), "l"(b));
}
__device__ __forceinline__ ull pack2(float x, float y)
{
    ull r;
    asm("mov.b64 %0, {%1, %2};" : "=l"(r) : "f"(x), "f"(y));
    return r;
}
__device__ __forceinline__ void unpack2(ull v, float& x, float& y)
{
    asm("mov.b64 {%0, %1}, %2;" : "=f"(x), "=f"(y) : "l"(v));
}

// ---------------------------------------------------------------------------
// Unified fp16 HMMA GEMM. A fp16 single; B fp16 single (BSPLIT=0) or hi/lo
// split (BSPLIT=1, 2 MMAs). CTA tile 128x128, BK=64, 8 warps (2m x 4n),
// warp tile 64x32. 3-stage cp.async pipeline.
// Stage: A[16K] + B[16K or 32K].
// OUT 0: fp16 out (+bias if non-null).
// OUT 1: fp32 out (+bias) AND per-channel BN stats via atomics.
// blockIdx = (nTile, mTile, branch)
// ---------------------------------------------------------------------------
template <int BSPLIT>
__device__ __forceinline__ void issue_hg(
    const f16* gA, const f16* gBh, const f16* gBl,
    int K, int Ntot, int c, uint32_t sb, int tid)
{
    const int kt = c * 64;
#pragma unroll
    for (int i = 0; i < 4; i++) {
        int idx = tid + i * 256;            // A: 128 rows x 8 16B-chunks
        int r = idx >> 3, ch = idx & 7;
        uint32_t off = (uint32_t)(r * 128 + ((ch ^ (r & 7)) << 4));
        cpa16(sb + off, gA + (size_t)r * K + kt + ch * 8);
    }
#pragma unroll
    for (int i = 0; i < 4; i++) {
        int idx = tid + i * 256;            // B: 64 rows x 16 16B-chunks
        int r = idx >> 4, ch = idx & 15;
        uint32_t off = (uint32_t)(r * 256 + ((ch ^ (r & 7)) << 4));
        size_t go = (size_t)(kt + r) * Ntot + ch * 8;
        cpa16(sb + 16384 + off, gBh + go);
        if (BSPLIT) cpa16(sb + 32768 + off, gBl + go);
    }
    cp_commit();
}

template <int BSPLIT, int OUT>
__global__ void __launch_bounds__(256)
hgemm(const f16* __restrict__ A, const f16* __restrict__ Bh,
      const f16* __restrict__ Bl, const float* __restrict__ bias,
      f16* __restrict__ Cs, float* __restrict__ Cf, float* __restrict__ stats,
      int K, int Ntot)
{
    constexpr int STAGE = 16384 + (BSPLIT ? 32768 : 16384);
    extern __shared__ char smem[];
    const uint32_t sb0 = s2u(smem);

    const int tid  = threadIdx.x;
    const int wid  = tid >> 5;
    const int lane = tid & 31;
    const int z     = blockIdx.z;
    const int mTile = blockIdx.y;
    const int nTile = blockIdx.x;

    const int m0 = (wid & 1) * 64;
    const int n0 = (wid >> 1) * 32;

    const size_t brA = (size_t)z * NPTS * K;
    const size_t brC = (size_t)z * NPTS * Ntot;
    const f16* gA  = A + brA + (size_t)mTile * 128 * K;
    const f16* gBh = Bh + (size_t)nTile * 128;
    const f16* gBl = BSPLIT ? Bl + (size_t)nTile * 128 : nullptr;

    float acc[4][4][4];
#pragma unroll
    for (int i = 0; i < 4; i++)
#pragma unroll
        for (int j = 0; j < 4; j++)
#pragma unroll
            for (int t = 0; t < 4; t++) acc[i][j][t] = 0.0f;

    const int nch = K >> 6;
    issue_hg<BSPLIT>(gA, gBh, gBl, K, Ntot, 0, sb0, tid);
    if (nch > 1)
        issue_hg<BSPLIT>(gA, gBh, gBl, K, Ntot, 1, sb0 + STAGE, tid);
    else
        cp_commit();

    int bufn = 2 % 3;
    for (int c = 0; c < nch; c++) {
        if (c + 2 < nch)
            issue_hg<BSPLIT>(gA, gBh, gBl, K, Ntot, c + 2,
                             sb0 + bufn * STAGE, tid);
        else
            cp_commit();
        bufn = bufn == 2 ? 0 : bufn + 1;
        cp_wait<2>();
        __syncthreads();

        const uint32_t sb = sb0 + (c % 3) * STAGE;
        const uint32_t sA = sb, sB = sb + 16384;

#pragma unroll
        for (int ks = 0; ks < 4; ks++) {
            uint32_t bh[4][2], bl[4][2];
#pragma unroll
            for (int pr = 0; pr < 2; pr++) {
                int k   = ks * 16 + (lane & 15);
                int chn = ((n0 + pr * 16) >> 3) + (lane >> 4);
                uint32_t ba = sB + (uint32_t)(k * 256 + ((chn ^ (k & 7)) << 4));
                uint32_t t[4];
                ldsm4t(t, ba);
                bh[pr * 2][0] = t[0]; bh[pr * 2][1] = t[1];
                bh[pr * 2 + 1][0] = t[2]; bh[pr * 2 + 1][1] = t[3];
                if (BSPLIT) {
                    ldsm4t(t, ba + 16384);
                    bl[pr * 2][0] = t[0]; bl[pr * 2][1] = t[1];
                    bl[pr * 2 + 1][0] = t[2]; bl[pr * 2 + 1][1] = t[3];
                }
            }
#pragma unroll
            for (int mf = 0; mf < 4; mf++) {
                int r   = m0 + mf * 16 + (lane & 15);
                int chk = ks * 2 + (lane >> 4);
                uint32_t aa = sA + (uint32_t)(r * 128 + ((chk ^ (r & 7)) << 4));
                uint32_t av[4];
                ldsm4(av, aa);
#pragma unroll
                for (int nf = 0; nf < 4; nf++) {
                    mma_hf(acc[mf][nf], av, bh[nf]);
                    if (BSPLIT) mma_hf(acc[mf][nf], av, bl[nf]);
                }
            }
        }
        __syncthreads();
    }

    const int g  = lane >> 2;
    const int tg = lane & 3;

    float ts[4][2], tq[4][2];
    if (OUT == 1) {
#pragma unroll
        for (int nf = 0; nf < 4; nf++)
            ts[nf][0] = ts[nf][1] = tq[nf][0] = tq[nf][1] = 0.0f;
    }

#pragma unroll
    for (int mf = 0; mf < 4; mf++) {
#pragma unroll
        for (int nf = 0; nf < 4; nf++) {
            int col = nTile * 128 + n0 + nf * 8 + tg * 2;
            float b0 = bias ? bias[col] : 0.0f;
            float b1 = bias ? bias[col + 1] : 0.0f;
#pragma unroll
            for (int hrow = 0; hrow < 2; hrow++) {
                int row = mTile * 128 + m0 + mf * 16 + g + hrow * 8;
                float v0 = acc[mf][nf][hrow * 2 + 0] + b0;
                float v1 = acc[mf][nf][hrow * 2 + 1] + b1;
                size_t o = brC + (size_t)row * Ntot + col;
                if (OUT == 1) {
                    *reinterpret_cast<float2*>(Cf + o) = make_float2(v0, v1);
                    ts[nf][0] += v0;  tq[nf][0] = fmaf(v0, v0, tq[nf][0]);
                    ts[nf][1] += v1;  tq[nf][1] = fmaf(v1, v1, tq[nf][1]);
                } else {
                    __half2 p = __floats2half2_rn(v0, v1);
                    *reinterpret_cast<__half2*>(Cs + o) = p;
                }
            }
        }
    }

    if (OUT == 1) {
        float* st = stats + (size_t)z * 2 * COUT;
#pragma unroll
        for (int nf = 0; nf < 4; nf++) {
#pragma unroll
            for (int p = 0; p < 2; p++) {
#pragma unroll
                for (int off = 4; off <= 16; off <<= 1) {
                    ts[nf][p] += __shfl_xor_sync(0xFFFFFFFFu, ts[nf][p], off);
                    tq[nf][p] += __shfl_xor_sync(0xFFFFFFFFu, tq[nf][p], off);
                }
            }
        }
        if (lane < 4) {
#pragma unroll
            for (int nf = 0; nf < 4; nf++) {
                int col = nTile * 128 + n0 + nf * 8 + tg * 2;
                atomicAdd(&st[col],            ts[nf][0]);
                atomicAdd(&st[col + 1],        ts[nf][1]);
                atomicAdd(&st[COUT + col],     tq[nf][0]);
                atomicAdd(&st[COUT + col + 1], tq[nf][1]);
            }
        }
    }
}

// ---------------------------------------------------------------------------
// Conversions
// ---------------------------------------------------------------------------
__global__ void __launch_bounds__(256)
conv_act_f16(const float* __restrict__ a0, const float* __restrict__ a1,
             f16* __restrict__ o, int n4)
{
    const int z = blockIdx.y;
    const float* a = z ? a1 : a0;
    const size_t off = (size_t)z * n4;
    int i = blockIdx.x * 256 + threadIdx.x;
    if (i < n4) {
        float4 v = reinterpret_cast<const float4*>(a)[i];
        __half2 p0 = __floats2half2_rn(v.x, v.y);
        __half2 p1 = __floats2half2_rn(v.z, v.w);
        uint2 pk;
        pk.x = *reinterpret_cast<uint32_t*>(&p0);
        pk.y = *reinterpret_cast<uint32_t*>(&p1);
        reinterpret_cast<uint2*>(o)[off + i] = pk;
    }
}

__global__ void __launch_bounds__(256)
split_w_f16(const float* __restrict__ in, f16* __restrict__ oh, f16* __restrict__ ol, int n)
{
    int i = blockIdx.x * 256 + threadIdx.x;
    if (i < n) {
        float v = in[i];
        f16 h = __float2half(v);
        oh[i] = h;
        if (ol) ol[i] = __float2half(v - __half2float(h));
    }
}

// ---------------------------------------------------------------------------
// KPConv aggregation, f32x2 packed-FMA. 128-thread CTA = 2 points;
// thread u in [0,64) handles channel pair (2u, 2u+1).
// Inner loop: 1 LDG.32 gather + 1 LDS.64 infl + 1 FFMA2 per (k,p).
// ---------------------------------------------------------------------------
__global__ void __launch_bounds__(128)
kpconv_agg2(const f16* __restrict__ hbuf,
            const float* __restrict__ coords0, const float* __restrict__ coords1,
            const int* __restrict__ neighb0, const int* __restrict__ neighb1,
            const float* __restrict__ kpts, f16* __restrict__ agg)
{
    const int z = blockIdx.z;
    const float* coords = z ? coords1 : coords0;
    const int*   neighb = z ? neighb1 : neighb0;
    const size_t brH = (size_t)z * NPTS * CMID;
    const size_t brA = (size_t)z * NPTS * PC;

    const int t   = threadIdx.x;
    const int pt  = t >> 6;
    const int u   = t & 63;
    const int n   = blockIdx.x * 2 + pt;

    __shared__ int   nb_s[2][KNB];
    __shared__ float rel_s[2][KNB][3];
    __shared__ __align__(8) ull ipack[2][KNB][16];

    if (u < KNB) nb_s[pt][u] = neighb[n * KNB + u];
    __syncthreads();
    for (int idx = u; idx < KNB * 3; idx += 64) {
        int k = idx / 3, d = idx % 3;
        rel_s[pt][k][d] = coords[(size_t)nb_s[pt][k] * 3 + d]
                        - coords[(size_t)n * 3 + d];
    }
    __syncthreads();
    for (int idx = u; idx < KNB * PKP; idx += 64) {
        int k = idx / PKP, p = idx % PKP;
        float dx = rel_s[pt][k][0] - kpts[p * 3 + 0];
        float dy = rel_s[pt][k][1] - kpts[p * 3 + 1];
        float dz = rel_s[pt][k][2] - kpts[p * 3 + 2];
        float d  = sqrtf(dx * dx + dy * dy + dz * dz);
        float iv = fmaxf(0.0f, 1.0f - d * 1.25f);   // EXTENT = 0.8
        ipack[pt][k][p] = pack2(iv, iv);
    }
    __syncthreads();

    ull acc2[PKP];
#pragma unroll
    for (int p = 0; p < PKP; p++) acc2[p] = 0ull;

    const int ch2 = u;
#pragma unroll 2
    for (int k = 0; k < KNB; k++) {
        __half2 hv = __ldg(reinterpret_cast<const __half2*>(
            hbuf + brH + (size_t)nb_s[pt][k] * CMID) + ch2);
        float2 f = __half22float2(hv);
        ull av = pack2(f.x, f.y);
        const ull* ip = ipack[pt][k];
#pragma unroll
        for (int p = 0; p < PKP; p++)
            fma2(acc2[p], av, ip[p]);
    }

    f16* o = agg + brA + (size_t)n * PC;
#pragma unroll
    for (int p = 0; p < PKP; p++) {
        float x, y;
        unpack2(acc2[p], x, y);
        __half2 hv = __floats2half2_rn(x, y);
        reinterpret_cast<__half2*>(o + (size_t)p * CMID)[ch2] = hv;
    }
}

// ---------------------------------------------------------------------------
// BatchNorm apply
// ---------------------------------------------------------------------------
__global__ void zero_stats(float* s)
{
    s[blockIdx.x * 1024 + threadIdx.x] = 0.0f;   // <<<2, 1024>>>
}

__global__ void __launch_bounds__(256)
bn_apply4(const float* __restrict__ ybase, const float* __restrict__ stats,
          const float* __restrict__ gamma, const float* __restrict__ beta,
          float* __restrict__ outbase)
{
    const int z = blockIdx.y;
    const float* y   = ybase + (size_t)z * NPTS * COUT;
    const float* st  = stats + (size_t)z * 2 * COUT;
    float*       out = outbase + (size_t)z * NPTS * COUT;

    const int i = blockIdx.x * blockDim.x + threadIdx.x;
    const int c = (i * 4) & (COUT - 1);
    float4 v = reinterpret_cast<const float4*>(y)[i];
    float r[4] = {v.x, v.y, v.z, v.w};
#pragma unroll
    for (int j = 0; j < 4; j++) {
        float mu  = st[c + j] * (1.0f / NPTS);
        float var = st[COUT + c + j] * (1.0f / NPTS) - mu * mu;
        float scale = rsqrtf(var + 1e-5f) * gamma[c + j];
        float t = (r[j] - mu) * scale + beta[c + j];
        r[j] = (t >= 0.0f) ? t : 0.1f * t;
    }
    reinterpret_cast<float4*>(out)[i] = make_float4(r[0], r[1], r[2], r[3]);
}

__global__ void copy_coords(const float* __restrict__ a, const float* __restrict__ b,
                            float* __restrict__ out)
{
    int i = blockIdx.x * blockDim.x + threadIdx.x;
    if (i < NPTS * 3) {
        out[i]            = a[i];
        out[NPTS * 3 + i] = b[i];
    }
}

// ---------------------------------------------------------------------------
// Launcher
// ---------------------------------------------------------------------------
#define SMEM_SPLIT  (3 * 49152)   // BSPLIT=1 stage 48KB
#define SMEM_SINGLE (3 * 32768)   // BSPLIT=0 stage 32KB

extern "C" void kernel_launch(void* const* d_in, const int* in_sizes, int n_in,
                              void* d_out, int out_size)
{
    (void)in_sizes; (void)n_in; (void)out_size;

    const float* src    = (const float*)d_in[0];
    const float* tgt    = (const float*)d_in[1];
    const float* sc     = (const float*)d_in[2];
    const float* tc     = (const float*)d_in[3];
    const int*   snb    = (const int*)  d_in[4];
    const int*   tnb    = (const int*)  d_in[5];
    const float* W_in   = (const float*)d_in[6];
    const float* b_in   = (const float*)d_in[7];
    const float* kpts   = (const float*)d_in[8];
    const float* kpw    = (const float*)d_in[9];
    const float* W_out  = (const float*)d_in[10];
    const float* b_out  = (const float*)d_in[11];
    const float* gamma  = (const float*)d_in[12];
    const float* beta   = (const float*)d_in[13];
    float* out = (float*)d_out;

    f16 *xs, *h, *ag, *md, *wi_h, *wi_l, *kw, *wo_h, *wo_l;
    float *y, *stats;
    cudaGetSymbolAddress((void**)&xs,   g_xs);
    cudaGetSymbolAddress((void**)&h,    g_h);
    cudaGetSymbolAddress((void**)&ag,   g_ag);
    cudaGetSymbolAddress((void**)&md,   g_md);
    cudaGetSymbolAddress((void**)&wi_h, g_wi_h);  cudaGetSymbolAddress((void**)&wi_l, g_wi_l);
    cudaGetSymbolAddress((void**)&kw,   g_kw);
    cudaGetSymbolAddress((void**)&wo_h, g_wo_h);  cudaGetSymbolAddress((void**)&wo_l, g_wo_l);
    cudaGetSymbolAddress((void**)&y, g_y);
    cudaGetSymbolAddress((void**)&stats, g_stats);

    cudaFuncSetAttribute((const void*)hgemm<1, 0>,
                         cudaFuncAttributeMaxDynamicSharedMemorySize, SMEM_SPLIT);
    cudaFuncSetAttribute((const void*)hgemm<0, 0>,
                         cudaFuncAttributeMaxDynamicSharedMemorySize, SMEM_SINGLE);
    cudaFuncSetAttribute((const void*)hgemm<1, 1>,
                         cudaFuncAttributeMaxDynamicSharedMemorySize, SMEM_SPLIT);

    // Weight preps
    split_w_f16<<<(CIN * CMID + 255) / 256, 256>>>(W_in, wi_h, wi_l, CIN * CMID);
    split_w_f16<<<(PC * CMID + 255) / 256, 256>>>(kpw, kw, nullptr, PC * CMID);
    split_w_f16<<<(CMID * COUT + 255) / 256, 256>>>(W_out, wo_h, wo_l, CMID * COUT);

    // Inputs -> fp16 (both branches)
    conv_act_f16<<<dim3((NPTS * CIN / 4 + 255) / 256, 2), 256>>>(
        src, tgt, xs, NPTS * CIN / 4);

    // Zero BN stats
    zero_stats<<<2, 1024>>>(stats);

    // GEMM1: h = x @ W_in + b_in (B split) -> fp16
    hgemm<1, 0><<<dim3(1, NPTS / 128, 2), 256, SMEM_SPLIT>>>(
        xs, wi_h, wi_l, b_in, h, nullptr, nullptr, CIN, CMID);

    // KPConv gather + aggregation -> agg fp16
    kpconv_agg2<<<dim3(NPTS / 2, 1, 2), 128>>>(h, sc, tc, snb, tnb, kpts, ag);

    // mid = agg @ kpw (B single fp16, 1 MMA) -> fp16
    hgemm<0, 0><<<dim3(1, NPTS / 128, 2), 256, SMEM_SINGLE>>>(
        ag, kw, nullptr, nullptr, md, nullptr, nullptr, PC, CMID);

    // y = mid @ W_out + b_out (B split) -> fp32 + fused BN stats
    hgemm<1, 1><<<dim3(COUT / 128, NPTS / 128, 2), 256, SMEM_SPLIT>>>(
        md, wo_h, wo_l, b_out, nullptr, y, stats, CMID, COUT);

    // BN normalize + LeakyReLU
    bn_apply4<<<dim3((NPTS * COUT / 4) / 256, 2), 256>>>(y, stats, gamma, beta, out);

    // coords pass-through
    copy_coords<<<(NPTS * 3 + 255) / 256, 256>>>(sc, tc, out + 2ull * NPTS * COUT);
}

// round 11
// speedup vs baseline: 2.9683x; 1.0012x over previous
#include <cuda_runtime.h>
#include <cuda_bf16.h>
#include <cuda_fp16.h>
#include <math.h>
#include <stdint.h>

#define NPTS 16384
#define KNB  32
#define PKP  15
#define CIN  256
#define CMID 128
#define COUT 512
#define PC   (PKP * CMID)   // 1920

typedef unsigned long long ull;
typedef __half f16;

// ---------------------------------------------------------------------------
// Scratch (device globals -- allocation-free)
// ---------------------------------------------------------------------------
__device__ __align__(128) f16   g_xs  [2ull * NPTS * CIN];                  // fp16
__device__ __align__(128) f16   g_h   [2ull * NPTS * CMID];                 // fp16
__device__ __align__(128) f16   g_ag  [2ull * NPTS * PC];                   // fp16
__device__ __align__(128) f16   g_md  [2ull * NPTS * CMID];                 // fp16
__device__ __align__(128) float g_y   [2ull * NPTS * COUT];
__device__ __align__(128) f16   g_wi_h[CIN * CMID],  g_wi_l[CIN * CMID];    // split
__device__ __align__(128) f16   g_kw  [PC * CMID];                          // single
__device__ __align__(128) f16   g_wo_h[CMID * COUT], g_wo_l[CMID * COUT];   // split
__device__ float g_stats[2 * 2 * COUT];

// ---------------------------------------------------------------------------
// PTX helpers
// ---------------------------------------------------------------------------
__device__ __forceinline__ uint32_t s2u(const void* p)
{
    return (uint32_t)__cvta_generic_to_shared(p);
}
__device__ __forceinline__ void cpa16(uint32_t s, const void* g)
{
    asm volatile("cp.async.cg.shared.global [%0], [%1], 16;" :: "r"(s), "l"(g));
}
__device__ __forceinline__ void cp_commit()
{
    asm volatile("cp.async.commit_group;" ::: "memory");
}
template <int N>
__device__ __forceinline__ void cp_wait()
{
    asm volatile("cp.async.wait_group %0;" :: "n"(N) : "memory");
}
__device__ __forceinline__ void ldsm4(uint32_t* r, uint32_t a)
{
    asm volatile("ldmatrix.sync.aligned.m8n8.x4.shared.b16 {%0,%1,%2,%3}, [%4];"
                 : "=r"(r[0]), "=r"(r[1]), "=r"(r[2]), "=r"(r[3]) : "r"(a));
}
__device__ __forceinline__ void ldsm4t(uint32_t* r, uint32_t a)
{
    asm volatile("ldmatrix.sync.aligned.m8n8.x4.trans.shared.b16 {%0,%1,%2,%3}, [%4];"
                 : "=r"(r[0]), "=r"(r[1]), "=r"(r[2]), "=r"(r[3]) : "r"(a));
}
__device__ __forceinline__ void mma_hf(float* c, const uint32_t* a, const uint32_t* b)
{
    asm volatile(
        "mma.sync.aligned.m16n8k16.row.col.f32.f16.f16.f32 "
        "{%0,%1,%2,%3}, {%4,%5,%6,%7}, {%8,%9}, {%0,%1,%2,%3};"
        : "+f"(c[0]), "+f"(c[1]), "+f"(c[2]), "+f"(c[3])
        : "r"(a[0]), "r"(a[1]), "r"(a[2]), "r"(a[3]), "r"(b[0]), "r"(b[1]));
}
__device__ __forceinline__ void fma2(ull& d, ull a, ull b)
{
    asm("fma.rn.f32x2 %0, %1, %2, %0;" : "+l"(d) : "l"(a), "l"(b));
}
__device__ __forceinline__ ull pack2(float x, float y)
{
    ull r;
    asm("mov.b64 %0, {%1, %2};" : "=l"(r) : "f"(x), "f"(y));
    return r;
}
__device__ __forceinline__ void unpack2(ull v, float& x, float& y)
{
    asm("mov.b64 {%0, %1}, %2;" : "=f"(x), "=f"(y) : "l"(v));
}

// ---------------------------------------------------------------------------
// Unified fp16 HMMA GEMM. A fp16 single; B fp16 single (BSPLIT=0) or hi/lo
// split (BSPLIT=1, 2 MMAs). CTA tile 128x128, BK=64, 8 warps (2m x 4n),
// warp tile 64x32. 3-stage cp.async pipeline.
// Stage: A[16K] + B[16K or 32K].
// OUT 0: fp16 out (+bias if non-null).
// OUT 1: fp32 out (+bias) AND per-channel BN stats via atomics.
// blockIdx = (nTile, mTile, branch)
// ---------------------------------------------------------------------------
template <int BSPLIT>
__device__ __forceinline__ void issue_hg(
    const f16* gA, const f16* gBh, const f16* gBl,
    int K, int Ntot, int c, uint32_t sb, int tid)
{
    const int kt = c * 64;
#pragma unroll
    for (int i = 0; i < 4; i++) {
        int idx = tid + i * 256;            // A: 128 rows x 8 16B-chunks
        int r = idx >> 3, ch = idx & 7;
        uint32_t off = (uint32_t)(r * 128 + ((ch ^ (r & 7)) << 4));
        cpa16(sb + off, gA + (size_t)r * K + kt + ch * 8);
    }
#pragma unroll
    for (int i = 0; i < 4; i++) {
        int idx = tid + i * 256;            // B: 64 rows x 16 16B-chunks
        int r = idx >> 4, ch = idx & 15;
        uint32_t off = (uint32_t)(r * 256 + ((ch ^ (r & 7)) << 4));
        size_t go = (size_t)(kt + r) * Ntot + ch * 8;
        cpa16(sb + 16384 + off, gBh + go);
        if (BSPLIT) cpa16(sb + 32768 + off, gBl + go);
    }
    cp_commit();
}

template <int BSPLIT, int OUT>
__global__ void __launch_bounds__(256)
hgemm(const f16* __restrict__ A, const f16* __restrict__ Bh,
      const f16* __restrict__ Bl, const float* __restrict__ bias,
      f16* __restrict__ Cs, float* __restrict__ Cf, float* __restrict__ stats,
      int K, int Ntot)
{
    constexpr int STAGE = 16384 + (BSPLIT ? 32768 : 16384);
    extern __shared__ char smem[];
    const uint32_t sb0 = s2u(smem);

    const int tid  = threadIdx.x;
    const int wid  = tid >> 5;
    const int lane = tid & 31;
    const int z     = blockIdx.z;
    const int mTile = blockIdx.y;
    const int nTile = blockIdx.x;

    const int m0 = (wid & 1) * 64;
    const int n0 = (wid >> 1) * 32;

    const size_t brA = (size_t)z * NPTS * K;
    const size_t brC = (size_t)z * NPTS * Ntot;
    const f16* gA  = A + brA + (size_t)mTile * 128 * K;
    const f16* gBh = Bh + (size_t)nTile * 128;
    const f16* gBl = BSPLIT ? Bl + (size_t)nTile * 128 : nullptr;

    float acc[4][4][4];
#pragma unroll
    for (int i = 0; i < 4; i++)
#pragma unroll
        for (int j = 0; j < 4; j++)
#pragma unroll
            for (int t = 0; t < 4; t++) acc[i][j][t] = 0.0f;

    const int nch = K >> 6;
    issue_hg<BSPLIT>(gA, gBh, gBl, K, Ntot, 0, sb0, tid);
    if (nch > 1)
        issue_hg<BSPLIT>(gA, gBh, gBl, K, Ntot, 1, sb0 + STAGE, tid);
    else
        cp_commit();

    int bufn = 2 % 3;
    for (int c = 0; c < nch; c++) {
        if (c + 2 < nch)
            issue_hg<BSPLIT>(gA, gBh, gBl, K, Ntot, c + 2,
                             sb0 + bufn * STAGE, tid);
        else
            cp_commit();
        bufn = bufn == 2 ? 0 : bufn + 1;
        cp_wait<2>();
        __syncthreads();

        const uint32_t sb = sb0 + (c % 3) * STAGE;
        const uint32_t sA = sb, sB = sb + 16384;

#pragma unroll
        for (int ks = 0; ks < 4; ks++) {
            uint32_t bh[4][2], bl[4][2];
#pragma unroll
            for (int pr = 0; pr < 2; pr++) {
                int k   = ks * 16 + (lane & 15);
                int chn = ((n0 + pr * 16) >> 3) + (lane >> 4);
                uint32_t ba = sB + (uint32_t)(k * 256 + ((chn ^ (k & 7)) << 4));
                uint32_t t[4];
                ldsm4t(t, ba);
                bh[pr * 2][0] = t[0]; bh[pr * 2][1] = t[1];
                bh[pr * 2 + 1][0] = t[2]; bh[pr * 2 + 1][1] = t[3];
                if (BSPLIT) {
                    ldsm4t(t, ba + 16384);
                    bl[pr * 2][0] = t[0]; bl[pr * 2][1] = t[1];
                    bl[pr * 2 + 1][0] = t[2]; bl[pr * 2 + 1][1] = t[3];
                }
            }
#pragma unroll
            for (int mf = 0; mf < 4; mf++) {
                int r   = m0 + mf * 16 + (lane & 15);
                int chk = ks * 2 + (lane >> 4);
                uint32_t aa = sA + (uint32_t)(r * 128 + ((chk ^ (r & 7)) << 4));
                uint32_t av[4];
                ldsm4(av, aa);
#pragma unroll
                for (int nf = 0; nf < 4; nf++) {
                    mma_hf(acc[mf][nf], av, bh[nf]);
                    if (BSPLIT) mma_hf(acc[mf][nf], av, bl[nf]);
                }
            }
        }
        __syncthreads();
    }

    const int g  = lane >> 2;
    const int tg = lane & 3;

    float ts[4][2], tq[4][2];
    if (OUT == 1) {
#pragma unroll
        for (int nf = 0; nf < 4; nf++)
            ts[nf][0] = ts[nf][1] = tq[nf][0] = tq[nf][1] = 0.0f;
    }

#pragma unroll
    for (int mf = 0; mf < 4; mf++) {
#pragma unroll
        for (int nf = 0; nf < 4; nf++) {
            int col = nTile * 128 + n0 + nf * 8 + tg * 2;
            float b0 = bias ? bias[col] : 0.0f;
            float b1 = bias ? bias[col + 1] : 0.0f;
#pragma unroll
            for (int hrow = 0; hrow < 2; hrow++) {
                int row = mTile * 128 + m0 + mf * 16 + g + hrow * 8;
                float v0 = acc[mf][nf][hrow * 2 + 0] + b0;
                float v1 = acc[mf][nf][hrow * 2 + 1] + b1;
                size_t o = brC + (size_t)row * Ntot + col;
                if (OUT == 1) {
                    *reinterpret_cast<float2*>(Cf + o) = make_float2(v0, v1);
                    ts[nf][0] += v0;  tq[nf][0] = fmaf(v0, v0, tq[nf][0]);
                    ts[nf][1] += v1;  tq[nf][1] = fmaf(v1, v1, tq[nf][1]);
                } else {
                    __half2 p = __floats2half2_rn(v0, v1);
                    *reinterpret_cast<__half2*>(Cs + o) = p;
                }
            }
        }
    }

    if (OUT == 1) {
        float* st = stats + (size_t)z * 2 * COUT;
#pragma unroll
        for (int nf = 0; nf < 4; nf++) {
#pragma unroll
            for (int p = 0; p < 2; p++) {
#pragma unroll
                for (int off = 4; off <= 16; off <<= 1) {
                    ts[nf][p] += __shfl_xor_sync(0xFFFFFFFFu, ts[nf][p], off);
                    tq[nf][p] += __shfl_xor_sync(0xFFFFFFFFu, tq[nf][p], off);
                }
            }
        }
        if (lane < 4) {
#pragma unroll
            for (int nf = 0; nf < 4; nf++) {
                int col = nTile * 128 + n0 + nf * 8 + tg * 2;
                atomicAdd(&st[col],            ts[nf][0]);
                atomicAdd(&st[col + 1],        ts[nf][1]);
                atomicAdd(&st[COUT + col],     tq[nf][0]);
                atomicAdd(&st[COUT + col + 1], tq[nf][1]);
            }
        }
    }
}

// ---------------------------------------------------------------------------
// Conversions
// ---------------------------------------------------------------------------
__global__ void __launch_bounds__(256)
conv_act_f16(const float* __restrict__ a0, const float* __restrict__ a1,
             f16* __restrict__ o, int n4)
{
    const int z = blockIdx.y;
    const float* a = z ? a1 : a0;
    const size_t off = (size_t)z * n4;
    int i = blockIdx.x * 256 + threadIdx.x;
    if (i < n4) {
        float4 v = reinterpret_cast<const float4*>(a)[i];
        __half2 p0 = __floats2half2_rn(v.x, v.y);
        __half2 p1 = __floats2half2_rn(v.z, v.w);
        uint2 pk;
        pk.x = *reinterpret_cast<uint32_t*>(&p0);
        pk.y = *reinterpret_cast<uint32_t*>(&p1);
        reinterpret_cast<uint2*>(o)[off + i] = pk;
    }
}

__global__ void __launch_bounds__(256)
split_w_f16(const float* __restrict__ in, f16* __restrict__ oh, f16* __restrict__ ol, int n)
{
    int i = blockIdx.x * 256 + threadIdx.x;
    if (i < n) {
        float v = in[i];
        f16 h = __float2half(v);
        oh[i] = h;
        if (ol) ol[i] = __float2half(v - __half2float(h));
    }
}

// ---------------------------------------------------------------------------
// KPConv aggregation, f32x2 packed-FMA. 128-thread CTA = 2 points;
// thread u in [0,64) handles channel pair (2u, 2u+1).
// Inner loop: 1 LDG.32 gather + 1 LDS.64 infl + 1 FFMA2 per (k,p).
// ---------------------------------------------------------------------------
__global__ void __launch_bounds__(128)
kpconv_agg2(const f16* __restrict__ hbuf,
            const float* __restrict__ coords0, const float* __restrict__ coords1,
            const int* __restrict__ neighb0, const int* __restrict__ neighb1,
            const float* __restrict__ kpts, f16* __restrict__ agg)
{
    const int z = blockIdx.z;
    const float* coords = z ? coords1 : coords0;
    const int*   neighb = z ? neighb1 : neighb0;
    const size_t brH = (size_t)z * NPTS * CMID;
    const size_t brA = (size_t)z * NPTS * PC;

    const int t   = threadIdx.x;
    const int pt  = t >> 6;
    const int u   = t & 63;
    const int n   = blockIdx.x * 2 + pt;

    __shared__ int   nb_s[2][KNB];
    __shared__ float rel_s[2][KNB][3];
    __shared__ __align__(8) ull ipack[2][KNB][16];

    if (u < KNB) nb_s[pt][u] = neighb[n * KNB + u];
    __syncthreads();
    for (int idx = u; idx < KNB * 3; idx += 64) {
        int k = idx / 3, d = idx % 3;
        rel_s[pt][k][d] = coords[(size_t)nb_s[pt][k] * 3 + d]
                        - coords[(size_t)n * 3 + d];
    }
    __syncthreads();
    for (int idx = u; idx < KNB * PKP; idx += 64) {
        int k = idx / PKP, p = idx % PKP;
        float dx = rel_s[pt][k][0] - kpts[p * 3 + 0];
        float dy = rel_s[pt][k][1] - kpts[p * 3 + 1];
        float dz = rel_s[pt][k][2] - kpts[p * 3 + 2];
        float d  = sqrtf(dx * dx + dy * dy + dz * dz);
        float iv = fmaxf(0.0f, 1.0f - d * 1.25f);   // EXTENT = 0.8
        ipack[pt][k][p] = pack2(iv, iv);
    }
    __syncthreads();

    ull acc2[PKP];
#pragma unroll
    for (int p = 0; p < PKP; p++) acc2[p] = 0ull;

    const int ch2 = u;
#pragma unroll 2
    for (int k = 0; k < KNB; k++) {
        __half2 hv = __ldg(reinterpret_cast<const __half2*>(
            hbuf + brH + (size_t)nb_s[pt][k] * CMID) + ch2);
        float2 f = __half22float2(hv);
        ull av = pack2(f.x, f.y);
        const ull* ip = ipack[pt][k];
#pragma unroll
        for (int p = 0; p < PKP; p++)
            fma2(acc2[p], av, ip[p]);
    }

    f16* o = agg + brA + (size_t)n * PC;
#pragma unroll
    for (int p = 0; p < PKP; p++) {
        float x, y;
        unpack2(acc2[p], x, y);
        __half2 hv = __floats2half2_rn(x, y);
        reinterpret_cast<__half2*>(o + (size_t)p * CMID)[ch2] = hv;
    }
}

// ---------------------------------------------------------------------------
// BatchNorm apply
// ---------------------------------------------------------------------------
__global__ void zero_stats(float* s)
{
    s[blockIdx.x * 1024 + threadIdx.x] = 0.0f;   // <<<2, 1024>>>
}

__global__ void __launch_bounds__(256)
bn_apply4(const float* __restrict__ ybase, const float* __restrict__ stats,
          const float* __restrict__ gamma, const float* __restrict__ beta,
          float* __restrict__ outbase)
{
    const int z = blockIdx.y;
    const float* y   = ybase + (size_t)z * NPTS * COUT;
    const float* st  = stats + (size_t)z * 2 * COUT;
    float*       out = outbase + (size_t)z * NPTS * COUT;

    const int i = blockIdx.x * blockDim.x + threadIdx.x;
    const int c = (i * 4) & (COUT - 1);
    float4 v = reinterpret_cast<const float4*>(y)[i];
    float r[4] = {v.x, v.y, v.z, v.w};
#pragma unroll
    for (int j = 0; j < 4; j++) {
        float mu  = st[c + j] * (1.0f / NPTS);
        float var = st[COUT + c + j] * (1.0f / NPTS) - mu * mu;
        float scale = rsqrtf(var + 1e-5f) * gamma[c + j];
        float t = (r[j] - mu) * scale + beta[c + j];
        r[j] = (t >= 0.0f) ? t : 0.1f * t;
    }
    reinterpret_cast<float4*>(out)[i] = make_float4(r[0], r[1], r[2], r[3]);
}

__global__ void copy_coords(const float* __restrict__ a, const float* __restrict__ b,
                            float* __restrict__ out)
{
    int i = blockIdx.x * blockDim.x + threadIdx.x;
    if (i < NPTS * 3) {
        out[i]            = a[i];
        out[NPTS * 3 + i] = b[i];
    }
}

// ---------------------------------------------------------------------------
// Launcher
// ---------------------------------------------------------------------------
#define SMEM_SPLIT  (3 * 49152)   // BSPLIT=1 stage 48KB
#define SMEM_SINGLE (3 * 32768)   // BSPLIT=0 stage 32KB

extern "C" void kernel_launch(void* const* d_in, const int* in_sizes, int n_in,
                              void* d_out, int out_size)
{
    (void)in_sizes; (void)n_in; (void)out_size;

    const float* src    = (const float*)d_in[0];
    const float* tgt    = (const float*)d_in[1];
    const float* sc     = (const float*)d_in[2];
    const float* tc     = (const float*)d_in[3];
    const int*   snb    = (const int*)  d_in[4];
    const int*   tnb    = (const int*)  d_in[5];
    const float* W_in   = (const float*)d_in[6];
    const float* b_in   = (const float*)d_in[7];
    const float* kpts   = (const float*)d_in[8];
    const float* kpw    = (const float*)d_in[9];
    const float* W_out  = (const float*)d_in[10];
    const float* b_out  = (const float*)d_in[11];
    const float* gamma  = (const float*)d_in[12];
    const float* beta   = (const float*)d_in[13];
    float* out = (float*)d_out;

    f16 *xs, *h, *ag, *md, *wi_h, *wi_l, *kw, *wo_h, *wo_l;
    float *y, *stats;
    cudaGetSymbolAddress((void**)&xs,   g_xs);
    cudaGetSymbolAddress((void**)&h,    g_h);
    cudaGetSymbolAddress((void**)&ag,   g_ag);
    cudaGetSymbolAddress((void**)&md,   g_md);
    cudaGetSymbolAddress((void**)&wi_h, g_wi_h);  cudaGetSymbolAddress((void**)&wi_l, g_wi_l);
    cudaGetSymbolAddress((void**)&kw,   g_kw);
    cudaGetSymbolAddress((void**)&wo_h, g_wo_h);  cudaGetSymbolAddress((void**)&wo_l, g_wo_l);
    cudaGetSymbolAddress((void**)&y, g_y);
    cudaGetSymbolAddress((void**)&stats, g_stats);

    cudaFuncSetAttribute((const void*)hgemm<1, 0>,
                         cudaFuncAttributeMaxDynamicSharedMemorySize, SMEM_SPLIT);
    cudaFuncSetAttribute((const void*)hgemm<0, 0>,
                         cudaFuncAttributeMaxDynamicSharedMemorySize, SMEM_SINGLE);
    cudaFuncSetAttribute((const void*)hgemm<1, 1>,
                         cudaFuncAttributeMaxDynamicSharedMemorySize, SMEM_SPLIT);

    // Weight preps
    split_w_f16<<<(CIN * CMID + 255) / 256, 256>>>(W_in, wi_h, wi_l, CIN * CMID);
    split_w_f16<<<(PC * CMID + 255) / 256, 256>>>(kpw, kw, nullptr, PC * CMID);
    split_w_f16<<<(CMID * COUT + 255) / 256, 256>>>(W_out, wo_h, wo_l, CMID * COUT);

    // Inputs -> fp16 (both branches)
    conv_act_f16<<<dim3((NPTS * CIN / 4 + 255) / 256, 2), 256>>>(
        src, tgt, xs, NPTS * CIN / 4);

    // Zero BN stats
    zero_stats<<<2, 1024>>>(stats);

    // GEMM1: h = x @ W_in + b_in (B split) -> fp16
    hgemm<1, 0><<<dim3(1, NPTS / 128, 2), 256, SMEM_SPLIT>>>(
        xs, wi_h, wi_l, b_in, h, nullptr, nullptr, CIN, CMID);

    // KPConv gather + aggregation -> agg fp16
    kpconv_agg2<<<dim3(NPTS / 2, 1, 2), 128>>>(h, sc, tc, snb, tnb, kpts, ag);

    // mid = agg @ kpw (B single fp16, 1 MMA) -> fp16
    hgemm<0, 0><<<dim3(1, NPTS / 128, 2), 256, SMEM_SINGLE>>>(
        ag, kw, nullptr, nullptr, md, nullptr, nullptr, PC, CMID);

    // y = mid @ W_out + b_out (B split) -> fp32 + fused BN stats
    hgemm<1, 1><<<dim3(COUT / 128, NPTS / 128, 2), 256, SMEM_SPLIT>>>(
        md, wo_h, wo_l, b_out, nullptr, y, stats, CMID, COUT);

    // BN normalize + LeakyReLU
    bn_apply4<<<dim3((NPTS * COUT / 4) / 256, 2), 256>>>(y, stats, gamma, beta, out);

    // coords pass-through
    copy_coords<<<(NPTS * 3 + 255) / 256, 256>>>(sc, tc, out + 2ull * NPTS * COUT);
}